// round 2
// baseline (speedup 1.0000x reference)
#include <cuda_runtime.h>
#include <math.h>

// ---------------------------------------------------------------------------
// PatchFSL: few-shot patch-similarity classifier.
//
// Key identity: v enters additively per support row, so
//   p[b,w] = LSE_{sp in w}( v[sp]/T + L[sp,b] ),
//   L[sp,b] = log sum_qp exp( dot(skn[sp], qn[b,qp]) / T )     (mask => exclude)
// We precompute L once (two exp-sum GEMMs), then run the 15 SGD steps on the
// tiny [4900 x 25] table in a single block, then the final LSE on [4900 x 75].
// ---------------------------------------------------------------------------

#define D      384
#define SEQ    196
#define NWAY   5
#define KSHOT  5
#define NSUP   25            // support images
#define NQRY   75            // query images
#define LS     (NSUP*SEQ)    // 4900 support patches
#define NCOLS_S (NSUP*SEQ)   // 4900 support-query patch columns
#define NCOLS_Q (NQRY*SEQ)   // 14700 query patch columns
#define PER_W  (KSHOT*SEQ)   // 980 support patches per class
#define OPT_STEPS 15
#define LRATE  0.1f
#define INVT   (1.0f/0.0510310363f)

static __device__ float g_skn[LS*D];
static __device__ float g_sqn[LS*D];
static __device__ float g_qn [NCOLS_Q*D];
static __device__ float g_E1 [LS*NSUP];   // exp-sums -> logs (training)
static __device__ float g_E2 [LS*NQRY];   // exp-sums -> logs (final)
static __device__ float g_v  [LS];

// --------------------------- row L2 normalize ------------------------------
__global__ void normalize_kernel(const float* __restrict__ in,
                                 float* __restrict__ out)
{
    int row = blockIdx.x;
    const float* src = in + (size_t)row * D;
    float ss = 0.f;
    for (int i = threadIdx.x; i < D; i += blockDim.x) {
        float x = src[i];
        ss += x * x;
    }
    __shared__ float sh[32];
    for (int o = 16; o; o >>= 1) ss += __shfl_down_sync(0xffffffffu, ss, o);
    if ((threadIdx.x & 31) == 0) sh[threadIdx.x >> 5] = ss;
    __syncthreads();
    if (threadIdx.x < 32) {
        float v2 = (threadIdx.x < (blockDim.x >> 5)) ? sh[threadIdx.x] : 0.f;
        for (int o = 16; o; o >>= 1) v2 += __shfl_down_sync(0xffffffffu, v2, o);
        if (threadIdx.x == 0) sh[0] = v2;
    }
    __syncthreads();
    float scale = 1.0f / fmaxf(sqrtf(sh[0]), 1e-8f);
    float* dst = out + (size_t)row * D;
    for (int i = threadIdx.x; i < D; i += blockDim.x) dst[i] = src[i] * scale;
}

__global__ void fill_zero_kernel(float* __restrict__ p, int n)
{
    int i = blockIdx.x * blockDim.x + threadIdx.x;
    if (i < n) p[i] = 0.f;
}

// ------------------ GEMM + exp + per-image segment sum ---------------------
// C = A[M,384] * B[N,384]^T ; E[r, c/196] += exp(C[r,c]/T)   (mask: skip when
// c/196 == r/196). 128x128x8 register-blocked fp32 GEMM, atomic epilogue.
__global__ __launch_bounds__(256)
void gemm_expsum_kernel(const float* __restrict__ A,
                        const float* __restrict__ B,
                        float* __restrict__ E,
                        int M, int N, int nseg, int applyMask)
{
    __shared__ float As[8][128];
    __shared__ float Bs[8][128];

    int tid  = threadIdx.x;
    int row0 = blockIdx.y * 128;
    int col0 = blockIdx.x * 128;

    int lm = tid >> 1;          // 0..127 row within tile
    int lk = (tid & 1) * 4;     // 0 or 4 within k-slab

    float acc[8][8];
#pragma unroll
    for (int i = 0; i < 8; i++)
#pragma unroll
        for (int j = 0; j < 8; j++) acc[i][j] = 0.f;

    int ttr = tid >> 4;         // 0..15
    int ttc = tid & 15;         // 0..15

    for (int k0 = 0; k0 < D; k0 += 8) {
        int ar = row0 + lm;
        float4 av = make_float4(0.f, 0.f, 0.f, 0.f);
        if (ar < M)
            av = *reinterpret_cast<const float4*>(A + (size_t)ar * D + k0 + lk);
        As[lk + 0][lm] = av.x; As[lk + 1][lm] = av.y;
        As[lk + 2][lm] = av.z; As[lk + 3][lm] = av.w;

        int br = col0 + lm;
        float4 bv = make_float4(0.f, 0.f, 0.f, 0.f);
        if (br < N)
            bv = *reinterpret_cast<const float4*>(B + (size_t)br * D + k0 + lk);
        Bs[lk + 0][lm] = bv.x; Bs[lk + 1][lm] = bv.y;
        Bs[lk + 2][lm] = bv.z; Bs[lk + 3][lm] = bv.w;

        __syncthreads();
#pragma unroll
        for (int k = 0; k < 8; k++) {
            float a[8], b[8];
#pragma unroll
            for (int i = 0; i < 8; i++) a[i] = As[k][ttr * 8 + i];
#pragma unroll
            for (int j = 0; j < 8; j++) b[j] = Bs[k][ttc * 8 + j];
#pragma unroll
            for (int i = 0; i < 8; i++)
#pragma unroll
                for (int j = 0; j < 8; j++) acc[i][j] += a[i] * b[j];
        }
        __syncthreads();
    }

    // Epilogue: exp(acc/T), aggregate per 196-column image segment, atomicAdd.
#pragma unroll
    for (int i = 0; i < 8; i++) {
        int r = row0 + ttr * 8 + i;
        if (r >= M) break;
        int rimg = r / SEQ;
        float segsum = 0.f;
        int curseg = -1;
#pragma unroll
        for (int j = 0; j < 8; j++) {
            int c = col0 + ttc * 8 + j;
            if (c >= N) break;
            int seg = c / SEQ;
            float e = __expf(acc[i][j] * INVT);
            if (applyMask && seg == rimg) e = 0.f;
            if (seg != curseg) {
                if (curseg >= 0) atomicAdd(&E[(size_t)r * nseg + curseg], segsum);
                curseg = seg;
                segsum = 0.f;
            }
            segsum += e;
        }
        if (curseg >= 0) atomicAdd(&E[(size_t)r * nseg + curseg], segsum);
    }
}

__global__ void log_kernel(float* __restrict__ p, int n)
{
    int i = blockIdx.x * blockDim.x + threadIdx.x;
    if (i < n) {
        float x = p[i];
        p[i] = (x > 0.f) ? logf(x) : -1e30f;
    }
}

// ------------------------- 15-step SGD on v --------------------------------
// Single block: all state in shared, __syncthreads between phases.
__global__ __launch_bounds__(1024)
void optimize_kernel(const float* __restrict__ Lsup,   // [LS][NSUP] logs
                     const int*   __restrict__ labels,
                     float*       __restrict__ v_out)
{
    __shared__ float sv[LS];
    __shared__ float p_sh[NSUP * NWAY];
    __shared__ float coef[NSUP * NWAY];

    int tid  = threadIdx.x;
    int warp = tid >> 5;
    int lane = tid & 31;

    for (int i = tid; i < LS; i += 1024) sv[i] = 0.f;
    __syncthreads();

    for (int step = 0; step < OPT_STEPS; ++step) {
        // phase 1: p[b,w] = LSE over 980 support rows of class w
        for (int pair = warp; pair < NSUP * NWAY; pair += 32) {
            int b = pair / NWAY, w = pair % NWAY;
            int base = w * PER_W;
            float m = -3.0e38f, s = 0.f;
            for (int idx = lane; idx < PER_W; idx += 32) {
                int sp = base + idx;
                float x = sv[sp] * INVT + Lsup[sp * NSUP + b];
                if (x > m) { s = s * __expf(m - x) + 1.0f; m = x; }
                else         s += __expf(x - m);
            }
            for (int o = 16; o; o >>= 1) {
                float om = __shfl_down_sync(0xffffffffu, m, o);
                float os = __shfl_down_sync(0xffffffffu, s, o);
                float nm = fmaxf(m, om);
                s = s * __expf(m - nm) + os * __expf(om - nm);
                m = nm;
            }
            if (lane == 0) p_sh[pair] = m + logf(s);
        }
        __syncthreads();

        // phase 2: coef[b,w] = (softmax(p[b,:])[w] - onehot) / B
        if (tid < NSUP) {
            int b = tid;
            float mm = -3.0e38f;
            for (int w = 0; w < NWAY; w++) mm = fmaxf(mm, p_sh[b * NWAY + w]);
            float e[NWAY], se = 0.f;
            for (int w = 0; w < NWAY; w++) {
                e[w] = __expf(p_sh[b * NWAY + w] - mm);
                se += e[w];
            }
            int lab = labels[b];
            for (int w = 0; w < NWAY; w++)
                coef[b * NWAY + w] = (e[w] / se - (w == lab ? 1.f : 0.f)) / (float)NSUP;
        }
        __syncthreads();

        // phase 3: grad and update
        for (int sp = tid; sp < LS; sp += 1024) {
            int w = sp / PER_W;
            float vv = sv[sp] * INVT;
            float g = 0.f;
            for (int b = 0; b < NSUP; b++) {
                g += coef[b * NWAY + w] *
                     __expf(vv + Lsup[sp * NSUP + b] - p_sh[b * NWAY + w]);
            }
            sv[sp] -= LRATE * (g * INVT);
        }
        __syncthreads();
    }

    for (int i = tid; i < LS; i += 1024) v_out[i] = sv[i];
}

// ----------------------------- final predict -------------------------------
__global__ __launch_bounds__(128)
void final_kernel(const float* __restrict__ Lq,   // [LS][NQRY] logs
                  const float* __restrict__ v,
                  float* __restrict__ out)        // [NQRY][NWAY]
{
    int pair = blockIdx.x;            // b*NWAY + w
    int b = pair / NWAY, w = pair % NWAY;
    int base = w * PER_W;
    int tid = threadIdx.x, lane = tid & 31, warp = tid >> 5;

    float m = -3.0e38f, s = 0.f;
    for (int idx = tid; idx < PER_W; idx += blockDim.x) {
        int sp = base + idx;
        float x = v[sp] * INVT + Lq[sp * NQRY + b];
        if (x > m) { s = s * __expf(m - x) + 1.0f; m = x; }
        else         s += __expf(x - m);
    }
    for (int o = 16; o; o >>= 1) {
        float om = __shfl_down_sync(0xffffffffu, m, o);
        float os = __shfl_down_sync(0xffffffffu, s, o);
        float nm = fmaxf(m, om);
        s = s * __expf(m - nm) + os * __expf(om - nm);
        m = nm;
    }
    __shared__ float sm[4], ss[4];
    if (lane == 0) { sm[warp] = m; ss[warp] = s; }
    __syncthreads();
    if (tid == 0) {
        float M = sm[0], S = ss[0];
        for (int i = 1; i < 4; i++) {
            float nm = fmaxf(M, sm[i]);
            S = S * __expf(M - nm) + ss[i] * __expf(sm[i] - nm);
            M = nm;
        }
        out[pair] = M + logf(S);
    }
}

// ---------------------------------------------------------------------------
extern "C" void kernel_launch(void* const* d_in, const int* in_sizes, int n_in,
                              void* d_out, int out_size)
{
    const float* sk  = (const float*)d_in[0];   // support_emb_key   [25,196,384]
    const float* sq  = (const float*)d_in[1];   // support_emb_query [25,196,384]
    const float* q   = (const float*)d_in[2];   // query_emb         [75,196,384]
    const int*   lab = (const int*)  d_in[3];   // support_labels    [25]
    float*       out = (float*)d_out;           // [75,5]

    float *skn, *sqn, *qn, *E1, *E2, *v;
    cudaGetSymbolAddress((void**)&skn, g_skn);
    cudaGetSymbolAddress((void**)&sqn, g_sqn);
    cudaGetSymbolAddress((void**)&qn,  g_qn);
    cudaGetSymbolAddress((void**)&E1,  g_E1);
    cudaGetSymbolAddress((void**)&E2,  g_E2);
    cudaGetSymbolAddress((void**)&v,   g_v);

    normalize_kernel<<<LS,      128>>>(sk, skn);
    normalize_kernel<<<LS,      128>>>(sq, sqn);
    normalize_kernel<<<NCOLS_Q, 128>>>(q,  qn);

    fill_zero_kernel<<<(LS*NSUP + 255) / 256, 256>>>(E1, LS*NSUP);
    fill_zero_kernel<<<(LS*NQRY + 255) / 256, 256>>>(E2, LS*NQRY);

    dim3 g1((NCOLS_S + 127) / 128, (LS + 127) / 128);
    gemm_expsum_kernel<<<g1, 256>>>(skn, sqn, E1, LS, NCOLS_S, NSUP, 1);
    dim3 g2((NCOLS_Q + 127) / 128, (LS + 127) / 128);
    gemm_expsum_kernel<<<g2, 256>>>(skn, qn,  E2, LS, NCOLS_Q, NQRY, 0);

    log_kernel<<<(LS*NSUP + 255) / 256, 256>>>(E1, LS*NSUP);
    log_kernel<<<(LS*NQRY + 255) / 256, 256>>>(E2, LS*NQRY);

    optimize_kernel<<<1, 1024>>>(E1, lab, v);

    final_kernel<<<NQRY * NWAY, 128>>>(E2, v, out);
}

// round 6
// speedup vs baseline: 2.4722x; 2.4722x over previous
#include <cuda_runtime.h>
#include <cuda_bf16.h>
#include <cstdint>
#include <math.h>

#define D       384
#define SEQ     196
#define NWAY    5
#define NSUP    25
#define NQRY    75
#define LS      4900
#define PER_W   980
#define KT      1152          // tripled K for bf16 hi/lo split
#define NCHUNK  18            // KT / 64
#define MPAD    4992          // 39*128
#define NTOT    19600         // 4900 + 14700
#define NPAD    19712         // 154*128
#define NSEG    100           // NTOT/SEQ
#define OPT_STEPS 15
#define LRATE   0.1f
#define INVT    (1.0f/0.0510310363f)
#define SCALE2  (INVT * 1.4426950408889634f)   // to exp2

static __device__ __align__(16) __nv_bfloat16 g_A[MPAD * KT];
static __device__ __align__(16) __nv_bfloat16 g_B[NPAD * KT];
static __device__ float g_E1t[NSUP * LS];   // [b][sp] raw exp-sums (masked)
static __device__ float g_E2t[NQRY * LS];   // [b][sp] raw exp-sums
static __device__ float g_e[LS];
static __device__ float g_mxc[NWAY];

__device__ __forceinline__ uint32_t smem_u32(const void* p) {
    uint32_t a;
    asm("{ .reg .u64 t; cvta.to.shared.u64 t, %1; cvt.u32.u64 %0, t; }"
        : "=r"(a) : "l"(p));
    return a;
}
#define SWZ(o) ((o) ^ (((o) >> 3) & 0x70))
#define CP16(dst, src)  asm volatile("cp.async.cg.shared.global [%0], [%1], 16;" :: "r"(dst), "l"(src))
#define CP_COMMIT()     asm volatile("cp.async.commit_group;" ::: "memory")
#define CP_WAIT1()      asm volatile("cp.async.wait_group 1;" ::: "memory")

__device__ __forceinline__ void ldmx4(uint32_t* r, uint32_t addr) {
    asm volatile("ldmatrix.sync.aligned.m8n8.x4.shared.b16 {%0,%1,%2,%3}, [%4];"
                 : "=r"(r[0]), "=r"(r[1]), "=r"(r[2]), "=r"(r[3]) : "r"(addr));
}
__device__ __forceinline__ void mma16816(float* d, const uint32_t* a,
                                         uint32_t b0, uint32_t b1) {
    asm volatile("mma.sync.aligned.m16n8k16.row.col.f32.bf16.bf16.f32 "
                 "{%0,%1,%2,%3}, {%4,%5,%6,%7}, {%8,%9}, {%0,%1,%2,%3};"
                 : "+f"(d[0]), "+f"(d[1]), "+f"(d[2]), "+f"(d[3])
                 : "r"(a[0]), "r"(a[1]), "r"(a[2]), "r"(a[3]), "r"(b0), "r"(b1));
}

// --------------------- normalize + bf16 hi/lo split ------------------------
// row layout (KT=1152): A -> [hi|lo|hi] (loPos=384), B -> [hi|hi|lo] (loPos=768)
// => C = hi.hi + lo.hi + hi.lo  (missing lo.lo term ~2^-18, negligible)
__global__ __launch_bounds__(128)
void conv_kernel(const float* __restrict__ src, __nv_bfloat16* __restrict__ dst,
                 int validRows, int loPos)
{
    int row = blockIdx.x, t = threadIdx.x;
    __nv_bfloat16* d = dst + (size_t)row * KT;
    if (row >= validRows) {
        __nv_bfloat16 z = __float2bfloat16(0.f);
        for (int i = t; i < KT; i += 128) d[i] = z;
        return;
    }
    const float* s = src + (size_t)row * D;
    float ss = 0.f;
    for (int i = t; i < D; i += 128) { float x = s[i]; ss += x * x; }
    __shared__ float sh[4];
    for (int o = 16; o; o >>= 1) ss += __shfl_down_sync(0xffffffffu, ss, o);
    if ((t & 31) == 0) sh[t >> 5] = ss;
    __syncthreads();
    float scale = 1.0f / fmaxf(sqrtf(sh[0] + sh[1] + sh[2] + sh[3]), 1e-8f);
    int hiPos2 = (loPos == 384) ? 768 : 384;
    for (int i = t; i < D; i += 128) {
        float x = s[i] * scale;
        __nv_bfloat16 h = __float2bfloat16(x);
        __nv_bfloat16 l = __float2bfloat16(x - __bfloat162float(h));
        d[i] = h; d[hiPos2 + i] = h; d[loPos + i] = l;
    }
}

__global__ void fill_zero_kernel(float* __restrict__ p, int n)
{
    int i = blockIdx.x * blockDim.x + threadIdx.x;
    if (i < n) p[i] = 0.f;
}

// ---------------------- HMMA GEMM + fused epilogue -------------------------
// CTA 128x128, 8 warps (2M x 4N), warp tile 64x32, K chunks of 64 bf16.
// smem: A0 @0, A1 @16K, B0 @32K, B1 @48K (SW128-swizzled 128B rows).
#define SM_TOTAL 65536

__device__ __forceinline__ void ep_flush(int seg, float sum, int r)
{
    if (seg < NSUP) atomicAdd(&g_E1t[seg * LS + r], sum);
    else            atomicAdd(&g_E2t[(seg - NSUP) * LS + r], sum);
}

__global__ __launch_bounds__(256, 2)
void gemm_kernel(const __nv_bfloat16* __restrict__ A,
                 const __nv_bfloat16* __restrict__ B)
{
    extern __shared__ char smem[];
    uint32_t sb = smem_u32(smem);
    int tid = threadIdx.x, wid = tid >> 5, lane = tid & 31;
    int row0 = blockIdx.y * 128;
    int col0 = blockIdx.x * 128;
    int wm = wid & 1, wn = wid >> 1;

    // per-thread cp.async mapping: row = tid>>1 (0..127), half = tid&1
    int ldrow = tid >> 1, ldhalf = tid & 1;
    const __nv_bfloat16* asrc = A + (size_t)(row0 + ldrow) * KT + ldhalf * 32;
    const __nv_bfloat16* bsrc = B + (size_t)(col0 + ldrow) * KT + ldhalf * 32;
    uint32_t dsto = ldrow * 128 + ldhalf * 64;

#define LOAD_CHUNK(c, buf) do {                                               \
        uint32_t _ab = sb + (buf) * 16384;                                    \
        uint32_t _bb = sb + 32768 + (buf) * 16384;                            \
        const __nv_bfloat16* _as = asrc + (c) * 64;                           \
        const __nv_bfloat16* _bs = bsrc + (c) * 64;                           \
        _Pragma("unroll")                                                     \
        for (int s = 0; s < 4; s++) {                                         \
            CP16(_ab + SWZ(dsto + s * 16), _as + s * 8);                      \
            CP16(_bb + SWZ(dsto + s * 16), _bs + s * 8);                      \
        }                                                                     \
        CP_COMMIT(); } while (0)

    float acc[4][4][4];
#pragma unroll
    for (int i = 0; i < 4; i++)
#pragma unroll
        for (int j = 0; j < 4; j++)
#pragma unroll
            for (int k = 0; k < 4; k++) acc[i][j][k] = 0.f;

    LOAD_CHUNK(0, 0);
    LOAD_CHUNK(1, 1);

    // ldmatrix address components (within-tile offsets, swizzled at use)
    int a_row = wm * 64 + (lane & 15);          // + mi*16
    int a_kb  = (lane >> 4) * 16;               // + ks*32
    int b_row = wn * 32 + (lane & 7) + ((lane >> 4) << 3);  // + nh*16
    int b_kb  = ((lane >> 3) & 1) * 16;         // + ks*32

    for (int c = 0; c < NCHUNK; c++) {
        CP_WAIT1();
        __syncthreads();
        uint32_t ab = sb + (c & 1) * 16384;
        uint32_t bb = sb + 32768 + (c & 1) * 16384;
#pragma unroll
        for (int ks = 0; ks < 2; ks++) {        // 2 k32 macro-steps = 4 k16
#pragma unroll
            for (int k2 = 0; k2 < 2; k2++) {
                int kb = (ks * 2 + k2) * 32;
                uint32_t areg[4][4], breg[2][4];
#pragma unroll
                for (int mi = 0; mi < 4; mi++)
                    ldmx4(areg[mi], ab + SWZ((a_row + mi * 16) * 128 + a_kb + kb));
#pragma unroll
                for (int nh = 0; nh < 2; nh++)
                    ldmx4(breg[nh], bb + SWZ((b_row + nh * 16) * 128 + b_kb + kb));
#pragma unroll
                for (int mi = 0; mi < 4; mi++)
#pragma unroll
                    for (int ni = 0; ni < 4; ni++)
                        mma16816(acc[mi][ni], areg[mi],
                                 breg[ni >> 1][(ni & 1) * 2],
                                 breg[ni >> 1][(ni & 1) * 2 + 1]);
            }
        }
        __syncthreads();
        if (c + 2 < NCHUNK) LOAD_CHUNK(c + 2, c & 1);
    }

    // ---------------- epilogue: exp + segment sums + atomics ----------------
    int colT = col0 + wn * 32;
    if (colT >= NTOT) return;
    int segA = colT / SEQ;
    int bcol = (segA + 1) * SEQ - colT;          // boundary offset within tile
    if (bcol > 32) bcol = 32;
    int segB = segA + 1;
    int cbase = (lane & 3) * 2;

#pragma unroll
    for (int mi = 0; mi < 4; mi++) {
#pragma unroll
        for (int half = 0; half < 2; half++) {
            int r = row0 + wm * 64 + mi * 16 + (lane >> 2) + half * 8;
            float sumA = 0.f, sumB = 0.f;
#pragma unroll
            for (int ni = 0; ni < 4; ni++) {
#pragma unroll
                for (int j = 0; j < 2; j++) {
                    int coff = ni * 8 + cbase + j;
                    float e = exp2f(acc[mi][ni][half * 2 + j] * SCALE2);
                    if (coff < bcol) sumA += e; else sumB += e;
                }
            }
            // quad reduce (lanes sharing lane>>2 have the same row)
            sumA += __shfl_xor_sync(0xffffffffu, sumA, 1);
            sumA += __shfl_xor_sync(0xffffffffu, sumA, 2);
            sumB += __shfl_xor_sync(0xffffffffu, sumB, 1);
            sumB += __shfl_xor_sync(0xffffffffu, sumB, 2);
            if ((lane & 3) == 0 && r < LS) {
                int rimg = r / SEQ;
                if (!(segA == rimg))               // E1 mask (segA<25 => rimg<25)
                    ep_flush(segA, sumA, r);
                if (bcol < 32 && segB < NSEG && !(segB == rimg))
                    ep_flush(segB, sumB, r);
            }
        }
    }
}

// ------------------------- optimizer (single block) ------------------------
__device__ __forceinline__ unsigned f2ord(float f) {
    unsigned u = __float_as_uint(f);
    return (u & 0x80000000u) ? ~u : (u | 0x80000000u);
}
__device__ __forceinline__ float ord2f(unsigned o) {
    unsigned u = (o & 0x80000000u) ? (o & 0x7FFFFFFFu) : ~o;
    return __uint_as_float(u);
}

__global__ __launch_bounds__(1024, 1)
void optimize_kernel(const float* __restrict__ E1t, const int* __restrict__ labels,
                     float* __restrict__ e_out, float* __restrict__ mxc_out)
{
    __shared__ float sv[LS];
    __shared__ float se[LS];
    __shared__ unsigned mxord[NWAY];
    __shared__ float mx[NWAY];
    __shared__ float Sw[30 * 25];
    __shared__ float Ssh[125], p_sh[125], cbv[125];

    int tid = threadIdx.x, warp = tid >> 5, lane = tid & 31;
    for (int i = tid; i < LS; i += 1024) sv[i] = 0.f;
    __syncthreads();

    for (int step = 0; step < OPT_STEPS; ++step) {
        if (tid < NWAY) mxord[tid] = 0;
        __syncthreads();
        for (int sp = tid; sp < LS; sp += 1024)
            atomicMax(&mxord[sp / PER_W], f2ord(sv[sp]));
        __syncthreads();
        if (tid < NWAY) mx[tid] = ord2f(mxord[tid]);
        __syncthreads();
        for (int sp = tid; sp < LS; sp += 1024)
            se[sp] = __expf((sv[sp] - mx[sp / PER_W]) * INVT);
        __syncthreads();

        // S[b,w] = sum_{sp in w} se[sp]*E1t[b][sp]; 30 warps = 5 classes x 6 chunks
        if (warp < 30) {
            int w = warp / 6, j = warp % 6;
            int start = j * 164;
            int lim = (j == 5) ? PER_W : start + 164;
            float ps[25];
#pragma unroll
            for (int b = 0; b < 25; b++) ps[b] = 0.f;
            for (int idx = start + lane; idx < lim; idx += 32) {
                int sp = w * PER_W + idx;
                float es = se[sp];
#pragma unroll
                for (int b = 0; b < 25; b++)
                    ps[b] += es * __ldg(&E1t[b * LS + sp]);
            }
#pragma unroll
            for (int b = 0; b < 25; b++)
                for (int o = 16; o; o >>= 1)
                    ps[b] += __shfl_down_sync(0xffffffffu, ps[b], o);
            if (lane == 0)
#pragma unroll
                for (int b = 0; b < 25; b++) Sw[warp * 25 + b] = ps[b];
        }
        __syncthreads();

        if (tid < 125) {
            int b = tid / 5, w = tid % 5;
            float s = 0.f;
#pragma unroll
            for (int u = 0; u < 6; u++) s += Sw[(w * 6 + u) * 25 + b];
            Ssh[tid] = s;
            p_sh[tid] = logf(s) + mx[w] * INVT;
        }
        __syncthreads();

        if (tid < NSUP) {
            int b = tid;
            float mm = -3.0e38f;
            for (int w = 0; w < NWAY; w++) mm = fmaxf(mm, p_sh[b * 5 + w]);
            float ev[NWAY], sesum = 0.f;
            for (int w = 0; w < NWAY; w++) {
                ev[w] = __expf(p_sh[b * 5 + w] - mm);
                sesum += ev[w];
            }
            int lab = labels[b];
            for (int w = 0; w < NWAY; w++)
                cbv[b * 5 + w] =
                    ((ev[w] / sesum - (w == lab ? 1.f : 0.f)) / (float)NSUP)
                    / Ssh[b * 5 + w];
        }
        __syncthreads();

        for (int sp = tid; sp < LS; sp += 1024) {
            int w = sp / PER_W;
            float es = se[sp], acc = 0.f;
#pragma unroll
            for (int b = 0; b < 25; b++)
                acc += cbv[b * 5 + w] * (es * __ldg(&E1t[b * LS + sp]));
            sv[sp] -= LRATE * INVT * acc;
        }
        __syncthreads();
    }

    if (tid < NWAY) mxord[tid] = 0;
    __syncthreads();
    for (int sp = tid; sp < LS; sp += 1024)
        atomicMax(&mxord[sp / PER_W], f2ord(sv[sp]));
    __syncthreads();
    if (tid < NWAY) { mx[tid] = ord2f(mxord[tid]); mxc_out[tid] = mx[tid] * INVT; }
    __syncthreads();
    for (int sp = tid; sp < LS; sp += 1024)
        e_out[sp] = __expf((sv[sp] - mx[sp / PER_W]) * INVT);
}

// ------------------------------- final LSE ---------------------------------
__global__ __launch_bounds__(128)
void final_kernel(const float* __restrict__ E2t, const float* __restrict__ e,
                  const float* __restrict__ mxc, float* __restrict__ out)
{
    int pair = blockIdx.x;              // b*5 + w
    int b = pair / NWAY, w = pair % NWAY;
    int base = w * PER_W;
    int tid = threadIdx.x;
    float s = 0.f;
    for (int idx = tid; idx < PER_W; idx += 128)
        s += e[base + idx] * E2t[b * LS + base + idx];
    __shared__ float sh[4];
    for (int o = 16; o; o >>= 1) s += __shfl_down_sync(0xffffffffu, s, o);
    if ((tid & 31) == 0) sh[tid >> 5] = s;
    __syncthreads();
    if (tid == 0)
        out[pair] = logf(sh[0] + sh[1] + sh[2] + sh[3]) + mxc[w];
}

// ---------------------------------------------------------------------------
extern "C" void kernel_launch(void* const* d_in, const int* in_sizes, int n_in,
                              void* d_out, int out_size)
{
    const float* sk  = (const float*)d_in[0];   // support_emb_key   [25,196,384]
    const float* sq  = (const float*)d_in[1];   // support_emb_query [25,196,384]
    const float* q   = (const float*)d_in[2];   // query_emb         [75,196,384]
    const int*   lab = (const int*)  d_in[3];   // support_labels    [25]
    float*       out = (float*)d_out;           // [75,5]

    __nv_bfloat16 *A, *B;
    float *E1t, *E2t, *ev, *mxc;
    cudaGetSymbolAddress((void**)&A,   g_A);
    cudaGetSymbolAddress((void**)&B,   g_B);
    cudaGetSymbolAddress((void**)&E1t, g_E1t);
    cudaGetSymbolAddress((void**)&E2t, g_E2t);
    cudaGetSymbolAddress((void**)&ev,  g_e);
    cudaGetSymbolAddress((void**)&mxc, g_mxc);

    cudaFuncSetAttribute(gemm_kernel,
                         cudaFuncAttributeMaxDynamicSharedMemorySize, SM_TOTAL);

    conv_kernel<<<MPAD, 128>>>(sk, A, LS, 384);                   // A: hi|lo|hi
    conv_kernel<<<LS, 128>>>(sq, B, LS, 768);                     // B: hi|hi|lo
    conv_kernel<<<NPAD - LS, 128>>>(q, B + (size_t)LS * KT, NTOT - LS, 768);

    fill_zero_kernel<<<(NSUP * LS + 255) / 256, 256>>>(E1t, NSUP * LS);
    fill_zero_kernel<<<(NQRY * LS + 255) / 256, 256>>>(E2t, NQRY * LS);

    dim3 grid(NPAD / 128, MPAD / 128);
    gemm_kernel<<<grid, 256, SM_TOTAL>>>(A, B);

    optimize_kernel<<<1, 1024>>>(E1t, lab, ev, mxc);
    final_kernel<<<NQRY * NWAY, 128>>>(E2t, ev, mxc, out);
}

// round 8
// speedup vs baseline: 2.9719x; 1.2021x over previous
#include <cuda_runtime.h>
#include <cuda_bf16.h>
#include <cstdint>
#include <math.h>

#define D       384
#define SEQ     196
#define NWAY    5
#define NSUP    25
#define NQRY    75
#define LS      4900
#define PER_W   980
#define KT      1152          // tripled K for bf16 hi/lo split
#define NCHUNK  18            // KT / 64
#define MPAD    4992          // 39*128
#define NTOT    19600         // 4900 + 14700
#define NPAD    19712         // 77*256
#define NSEG    100
#define OPT_STEPS 15
#define NOPT    25            // optimizer CTAs (one per support image)
#define LRATE   0.1f
#define INVT    (1.0f/0.0510310363f)
#define SCALE2  (INVT * 1.4426950408889634f)

static __device__ __align__(16) __nv_bfloat16 g_A[MPAD * KT];
static __device__ __align__(16) __nv_bfloat16 g_B[NPAD * KT];
static __device__ float g_E1t[NSUP * LS];   // [b][sp] raw exp-sums (masked)
static __device__ float g_E2t[NQRY * LS];   // [b][sp]
static __device__ float g_e[LS];
static __device__ float g_mxc[NWAY];
// optimizer cross-CTA scratch (zeroed by zero_scratch_kernel each run)
static __device__ unsigned g_bar[2 * OPT_STEPS + 1];
static __device__ unsigned g_gmax[(OPT_STEPS + 1) * NWAY];   // ordered-float max
static __device__ float    g_gS[OPT_STEPS * NSUP * NWAY];

__device__ __forceinline__ uint32_t smem_u32(const void* p) {
    uint32_t a;
    asm("{ .reg .u64 t; cvta.to.shared.u64 t, %1; cvt.u32.u64 %0, t; }"
        : "=r"(a) : "l"(p));
    return a;
}
#define SWZ(o) ((o) ^ (((o) >> 3) & 0x70))
#define CP16(dst, src)  asm volatile("cp.async.cg.shared.global [%0], [%1], 16;" :: "r"(dst), "l"(src))
#define CP_COMMIT()     asm volatile("cp.async.commit_group;" ::: "memory")
#define CP_WAIT1()      asm volatile("cp.async.wait_group 1;" ::: "memory")

__device__ __forceinline__ void ldmx4(uint32_t* r, uint32_t addr) {
    asm volatile("ldmatrix.sync.aligned.m8n8.x4.shared.b16 {%0,%1,%2,%3}, [%4];"
                 : "=r"(r[0]), "=r"(r[1]), "=r"(r[2]), "=r"(r[3]) : "r"(addr));
}
__device__ __forceinline__ void mma16816(float* d, const uint32_t* a,
                                         uint32_t b0, uint32_t b1) {
    asm volatile("mma.sync.aligned.m16n8k16.row.col.f32.bf16.bf16.f32 "
                 "{%0,%1,%2,%3}, {%4,%5,%6,%7}, {%8,%9}, {%0,%1,%2,%3};"
                 : "+f"(d[0]), "+f"(d[1]), "+f"(d[2]), "+f"(d[3])
                 : "r"(a[0]), "r"(a[1]), "r"(a[2]), "r"(a[3]), "r"(b0), "r"(b1));
}
__device__ __forceinline__ unsigned f2ord(float f) {
    unsigned u = __float_as_uint(f);
    return (u & 0x80000000u) ? ~u : (u | 0x80000000u);
}
__device__ __forceinline__ float ord2f(unsigned o) {
    unsigned u = (o & 0x80000000u) ? (o & 0x7FFFFFFFu) : ~o;
    return __uint_as_float(u);
}

// ------------- launch #1: normalize + bf16 hi/lo split (merged) ------------
// A rows (block < MPAD): [hi|lo|hi]; B rows: [hi|hi|lo]
__global__ __launch_bounds__(128)
void conv_all_kernel(const float* __restrict__ sk, const float* __restrict__ sq,
                     const float* __restrict__ q)
{
    int blk = blockIdx.x, t = threadIdx.x;
    const float* src;
    __nv_bfloat16* d;
    int loPos;
    if (blk < MPAD) {
        d = g_A + (size_t)blk * KT; loPos = 384;
        src = (blk < LS) ? sk + (size_t)blk * D : nullptr;
    } else {
        int j = blk - MPAD;
        d = g_B + (size_t)j * KT; loPos = 768;
        if (j < LS)        src = sq + (size_t)j * D;
        else if (j < NTOT) src = q + (size_t)(j - LS) * D;
        else               src = nullptr;
    }
    if (!src) {
        __nv_bfloat16 z = __float2bfloat16(0.f);
        for (int i = t; i < KT; i += 128) d[i] = z;
        return;
    }
    float ss = 0.f;
    for (int i = t; i < D; i += 128) { float x = src[i]; ss += x * x; }
    __shared__ float sh[4];
    for (int o = 16; o; o >>= 1) ss += __shfl_down_sync(0xffffffffu, ss, o);
    if ((t & 31) == 0) sh[t >> 5] = ss;
    __syncthreads();
    float scale = 1.0f / fmaxf(sqrtf(sh[0] + sh[1] + sh[2] + sh[3]), 1e-8f);
    int hiPos2 = (loPos == 384) ? 768 : 384;
    for (int i = t; i < D; i += 128) {
        float x = src[i] * scale;
        __nv_bfloat16 h = __float2bfloat16(x);
        __nv_bfloat16 l = __float2bfloat16(x - __bfloat162float(h));
        d[i] = h; d[hiPos2 + i] = h; d[loPos + i] = l;
    }
}

// ------------------- launch #2: zero E tables (merged) ---------------------
__global__ void fill_all_kernel()
{
    int i = blockIdx.x * blockDim.x + threadIdx.x;
    if (i < NSUP * LS) g_E1t[i] = 0.f;
    int j = i - NSUP * LS;
    if (j >= 0 && j < NQRY * LS) g_E2t[j] = 0.f;
}

// ---------------- launch #3: zero optimizer scratch (tiny) -----------------
__global__ void zero_scratch_kernel()
{
    int i = threadIdx.x;
    for (int k = i; k < 2 * OPT_STEPS + 1; k += 256) g_bar[k] = 0u;
    for (int k = i; k < (OPT_STEPS + 1) * NWAY; k += 256) g_gmax[k] = 0u;
    for (int k = i; k < OPT_STEPS * NSUP * NWAY; k += 256) g_gS[k] = 0.f;
}

// ------------- launch #4: HMMA GEMM 128x256 + fused epilogue ---------------
// 512 threads, 16 warps (2M x 8N), warp tile 64x32, K chunks of 64 bf16.
// smem: A0 @0 (16K), A1 @16K, B0 @32K (32K), B1 @64K. Total 96K.
#define SM_TOTAL 98304

__device__ __forceinline__ void ep_flush(int seg, float sum, int r)
{
    if (seg < NSUP) atomicAdd(&g_E1t[seg * LS + r], sum);
    else            atomicAdd(&g_E2t[(seg - NSUP) * LS + r], sum);
}

__global__ __launch_bounds__(512, 1)
void gemm_kernel(const __nv_bfloat16* __restrict__ A,
                 const __nv_bfloat16* __restrict__ B)
{
    extern __shared__ char smem[];
    uint32_t sb = smem_u32(smem);
    int tid = threadIdx.x, wid = tid >> 5, lane = tid & 31;
    int row0 = blockIdx.y * 128;
    int col0 = blockIdx.x * 256;
    int wm = wid & 1, wn = wid >> 1;

    // cp.async mapping: A 2 segs/thread, B 4 segs/thread
    int arow = tid >> 2, aseg = (tid & 3) * 2;
    int brow = tid >> 1, bseg = (tid & 1) * 4;
    const __nv_bfloat16* asrc = A + (size_t)(row0 + arow) * KT + aseg * 8;
    const __nv_bfloat16* bsrc = B + (size_t)(col0 + brow) * KT + bseg * 8;
    uint32_t adsto = arow * 128 + aseg * 16;
    uint32_t bdsto = brow * 128 + bseg * 16;

#define LOAD_CHUNK(c, buf) do {                                               \
        uint32_t _ab = sb + (buf) * 16384;                                    \
        uint32_t _bb = sb + 32768 + (buf) * 32768;                            \
        const __nv_bfloat16* _as = asrc + (c) * 64;                           \
        const __nv_bfloat16* _bs = bsrc + (c) * 64;                           \
        CP16(_ab + SWZ(adsto),      _as);                                     \
        CP16(_ab + SWZ(adsto + 16), _as + 8);                                 \
        CP16(_bb + SWZ(bdsto),      _bs);                                     \
        CP16(_bb + SWZ(bdsto + 16), _bs + 8);                                 \
        CP16(_bb + SWZ(bdsto + 32), _bs + 16);                                \
        CP16(_bb + SWZ(bdsto + 48), _bs + 24);                                \
        CP_COMMIT(); } while (0)

    float acc[4][4][4];
#pragma unroll
    for (int i = 0; i < 4; i++)
#pragma unroll
        for (int j = 0; j < 4; j++)
#pragma unroll
            for (int k = 0; k < 4; k++) acc[i][j][k] = 0.f;

    LOAD_CHUNK(0, 0);
    LOAD_CHUNK(1, 1);

    int a_row = wm * 64 + (lane & 15);
    int a_kb  = (lane >> 4) * 16;
    int b_row = wn * 32 + (lane & 7) + ((lane >> 4) << 3);
    int b_kb  = ((lane >> 3) & 1) * 16;

    for (int c = 0; c < NCHUNK; c++) {
        CP_WAIT1();
        __syncthreads();
        uint32_t ab = sb + (c & 1) * 16384;
        uint32_t bb = sb + 32768 + (c & 1) * 32768;
#pragma unroll
        for (int ks = 0; ks < 4; ks++) {            // 4 k16 steps per chunk
            int kb = ks * 32;
            uint32_t areg[4][4], breg[2][4];
#pragma unroll
            for (int mi = 0; mi < 4; mi++)
                ldmx4(areg[mi], ab + SWZ((a_row + mi * 16) * 128 + a_kb + kb));
#pragma unroll
            for (int nh = 0; nh < 2; nh++)
                ldmx4(breg[nh], bb + SWZ((b_row + nh * 16) * 128 + b_kb + kb));
#pragma unroll
            for (int mi = 0; mi < 4; mi++)
#pragma unroll
                for (int ni = 0; ni < 4; ni++)
                    mma16816(acc[mi][ni], areg[mi],
                             breg[ni >> 1][(ni & 1) * 2],
                             breg[ni >> 1][(ni & 1) * 2 + 1]);
        }
        __syncthreads();
        if (c + 2 < NCHUNK) LOAD_CHUNK(c + 2, c & 1);
    }

    // epilogue: exp + per-image segment sums + atomics
    int colT = col0 + wn * 32;
    if (colT >= NTOT) return;
    int segA = colT / SEQ;
    int bcol = (segA + 1) * SEQ - colT;
    if (bcol > 32) bcol = 32;
    int segB = segA + 1;
    int cbase = (lane & 3) * 2;

#pragma unroll
    for (int mi = 0; mi < 4; mi++) {
#pragma unroll
        for (int half = 0; half < 2; half++) {
            int r = row0 + wm * 64 + mi * 16 + (lane >> 2) + half * 8;
            float sumA = 0.f, sumB = 0.f;
#pragma unroll
            for (int ni = 0; ni < 4; ni++) {
#pragma unroll
                for (int j = 0; j < 2; j++) {
                    int coff = ni * 8 + cbase + j;
                    float e = exp2f(acc[mi][ni][half * 2 + j] * SCALE2);
                    if (coff < bcol) sumA += e; else sumB += e;
                }
            }
            sumA += __shfl_xor_sync(0xffffffffu, sumA, 1);
            sumA += __shfl_xor_sync(0xffffffffu, sumA, 2);
            sumB += __shfl_xor_sync(0xffffffffu, sumB, 1);
            sumB += __shfl_xor_sync(0xffffffffu, sumB, 2);
            if ((lane & 3) == 0 && r < LS) {
                int rimg = r / SEQ;
                if (segA != rimg)
                    ep_flush(segA, sumA, r);
                if (bcol < 32 && segB < NSEG && segB != rimg)
                    ep_flush(segB, sumB, r);
            }
        }
    }
}

// ------------- launch #5: optimizer, 25 CTAs + grid barriers ---------------
__device__ __forceinline__ void gridbar(int i)
{
    __syncthreads();
    if (threadIdx.x == 0) {
        __threadfence();
        unsigned o = atomicAdd(&g_bar[i], 1u);
        if (o + 1 < NOPT) {
            while (atomicAdd(&g_bar[i], 0u) < NOPT) __nanosleep(64);
        }
        __threadfence();
    }
    __syncthreads();
}

__global__ __launch_bounds__(256, 1)
void optimize_kernel(const int* __restrict__ labels)
{
    __shared__ float Esl[NSUP][SEQ];    // this image's E1t slice, all b
    __shared__ float vsl[SEQ], sesl[SEQ];
    __shared__ float cb[NSUP];
    __shared__ float red[8];

    int img = blockIdx.x;               // 0..24
    int w = img / 5;                    // its class
    int tid = threadIdx.x, warp = tid >> 5, lane = tid & 31;

    for (int b = 0; b < NSUP; b++)
        for (int t = tid; t < SEQ; t += 256)
            Esl[b][t] = g_E1t[b * LS + img * SEQ + t];
    for (int t = tid; t < SEQ; t += 256) vsl[t] = 0.f;
    __syncthreads();

    for (int step = 0; step < OPT_STEPS; ++step) {
        // phase 1: class max of v (local slice) -> global atomicMax
        float m = -3.0e38f;
        for (int t = tid; t < SEQ; t += 256) m = fmaxf(m, vsl[t]);
        for (int o = 16; o; o >>= 1)
            m = fmaxf(m, __shfl_xor_sync(0xffffffffu, m, o));
        if (lane == 0) red[warp] = m;
        __syncthreads();
        if (tid == 0) {
            float mm = red[0];
            for (int u = 1; u < 8; u++) mm = fmaxf(mm, red[u]);
            atomicMax(&g_gmax[step * NWAY + w], f2ord(mm));
        }
        gridbar(2 * step);

        // phase 2: se + partial S[b,w] for our class
        float mx = ord2f(g_gmax[step * NWAY + w]);
        for (int t = tid; t < SEQ; t += 256)
            sesl[t] = __expf((vsl[t] - mx) * INVT);
        __syncthreads();
        for (int b = warp; b < NSUP; b += 8) {
            float s = 0.f;
            for (int t = lane; t < SEQ; t += 32) s += sesl[t] * Esl[b][t];
            for (int o = 16; o; o >>= 1) s += __shfl_down_sync(0xffffffffu, s, o);
            if (lane == 0) atomicAdd(&g_gS[step * 125 + b * NWAY + w], s);
        }
        gridbar(2 * step + 1);

        // phase 3: per-b softmax coeffs (for our class), then local update
        if (tid < NSUP) {
            int b = tid;
            float p[NWAY], mm = -3.0e38f;
            for (int wp = 0; wp < NWAY; wp++) {
                p[wp] = logf(g_gS[step * 125 + b * NWAY + wp]) +
                        ord2f(g_gmax[step * NWAY + wp]) * INVT;
                mm = fmaxf(mm, p[wp]);
            }
            float ex[NWAY], se = 0.f;
            for (int wp = 0; wp < NWAY; wp++) { ex[wp] = __expf(p[wp] - mm); se += ex[wp]; }
            int lab = labels[b];
            float coef = (ex[w] / se - (w == lab ? 1.f : 0.f)) / (float)NSUP;
            cb[b] = coef / g_gS[step * 125 + b * NWAY + w];
        }
        __syncthreads();
        for (int t = tid; t < SEQ; t += 256) {
            float g = 0.f;
#pragma unroll
            for (int b = 0; b < NSUP; b++) g += cb[b] * Esl[b][t];
            vsl[t] -= LRATE * INVT * sesl[t] * g;
        }
        __syncthreads();
    }

    // final export: class max, e = exp((v-mx)/T), mxc = mx/T
    {
        float m = -3.0e38f;
        for (int t = tid; t < SEQ; t += 256) m = fmaxf(m, vsl[t]);
        for (int o = 16; o; o >>= 1)
            m = fmaxf(m, __shfl_xor_sync(0xffffffffu, m, o));
        if (lane == 0) red[warp] = m;
        __syncthreads();
        if (tid == 0) {
            float mm = red[0];
            for (int u = 1; u < 8; u++) mm = fmaxf(mm, red[u]);
            atomicMax(&g_gmax[OPT_STEPS * NWAY + w], f2ord(mm));
        }
        gridbar(2 * OPT_STEPS);
        float mx = ord2f(g_gmax[OPT_STEPS * NWAY + w]);
        for (int t = tid; t < SEQ; t += 256)
            g_e[img * SEQ + t] = __expf((vsl[t] - mx) * INVT);
        if (tid == 0) g_mxc[w] = mx * INVT;
    }
}

// --------------------------- launch #6: final LSE --------------------------
__global__ __launch_bounds__(128)
void final_kernel(float* __restrict__ out)
{
    int pair = blockIdx.x;              // b*5 + w
    int b = pair / NWAY, w = pair % NWAY;
    int base = w * PER_W;
    int tid = threadIdx.x;
    float s = 0.f;
    for (int idx = tid; idx < PER_W; idx += 128)
        s += g_e[base + idx] * g_E2t[b * LS + base + idx];
    __shared__ float sh[4];
    for (int o = 16; o; o >>= 1) s += __shfl_down_sync(0xffffffffu, s, o);
    if ((tid & 31) == 0) sh[tid >> 5] = s;
    __syncthreads();
    if (tid == 0)
        out[pair] = logf(sh[0] + sh[1] + sh[2] + sh[3]) + g_mxc[w];
}

// ---------------------------------------------------------------------------
extern "C" void kernel_launch(void* const* d_in, const int* in_sizes, int n_in,
                              void* d_out, int out_size)
{
    const float* sk  = (const float*)d_in[0];
    const float* sq  = (const float*)d_in[1];
    const float* q   = (const float*)d_in[2];
    const int*   lab = (const int*)  d_in[3];
    float*       out = (float*)d_out;

    __nv_bfloat16 *A, *B;
    cudaGetSymbolAddress((void**)&A, g_A);
    cudaGetSymbolAddress((void**)&B, g_B);

    cudaFuncSetAttribute(gemm_kernel,
                         cudaFuncAttributeMaxDynamicSharedMemorySize, SM_TOTAL);

    conv_all_kernel<<<MPAD + NPAD, 128>>>(sk, sq, q);                  // #1
    fill_all_kernel<<<((NSUP + NQRY) * LS + 255) / 256, 256>>>();      // #2
    zero_scratch_kernel<<<1, 256>>>();                                 // #3
    dim3 grid(NPAD / 256, MPAD / 128);
    gemm_kernel<<<grid, 512, SM_TOTAL>>>(A, B);                        // #4
    optimize_kernel<<<NOPT, 256>>>(lab);                               // #5
    final_kernel<<<NQRY * NWAY, 128>>>(out);                           // #6
}

// round 9
// speedup vs baseline: 4.1764x; 1.4053x over previous
#include <cuda_runtime.h>
#include <cuda_fp16.h>
#include <cstdint>
#include <math.h>

#define D       384
#define SEQ     196
#define NWAY    5
#define NSUP    25
#define NQRY    75
#define LS      4900
#define PER_W   980
#define KT      768           // doubled K for fp16 hi/lo split (2-term)
#define NCHUNK  12            // KT / 64
#define MPAD    4992          // 39*128
#define NTOT    19600         // 4900 + 14700
#define NPAD    19712         // 77*256
#define NSEG    100
#define OPT_STEPS 15
#define NOPT    25
#define LRATE   0.1f
#define INVT    (1.0f/0.0510310363f)
#define SCALE2  (INVT * 1.4426950408889634f)

static __device__ __align__(16) __half g_A[MPAD * KT];   // [hi|lo]
static __device__ __align__(16) __half g_B[NPAD * KT];   // [hi|hi]
static __device__ float g_E1t[NSUP * LS];   // [b][sp] raw exp-sums (masked)
static __device__ float g_E2t[NQRY * LS];   // [b][sp]
static __device__ float g_e[LS];
static __device__ float g_mxc[NWAY];
static __device__ unsigned g_bar[2 * OPT_STEPS + 1];
static __device__ unsigned g_gmax[(OPT_STEPS + 1) * NWAY];
static __device__ float    g_gS[OPT_STEPS * NSUP * NWAY];

__device__ __forceinline__ uint32_t smem_u32(const void* p) {
    uint32_t a;
    asm("{ .reg .u64 t; cvta.to.shared.u64 t, %1; cvt.u32.u64 %0, t; }"
        : "=r"(a) : "l"(p));
    return a;
}
#define SWZ(o) ((o) ^ (((o) >> 3) & 0x70))
#define CP16(dst, src)  asm volatile("cp.async.cg.shared.global [%0], [%1], 16;" :: "r"(dst), "l"(src))
#define CP_COMMIT()     asm volatile("cp.async.commit_group;" ::: "memory")
#define CP_WAIT1()      asm volatile("cp.async.wait_group 1;" ::: "memory")

__device__ __forceinline__ void ldmx4(uint32_t* r, uint32_t addr) {
    asm volatile("ldmatrix.sync.aligned.m8n8.x4.shared.b16 {%0,%1,%2,%3}, [%4];"
                 : "=r"(r[0]), "=r"(r[1]), "=r"(r[2]), "=r"(r[3]) : "r"(addr));
}
__device__ __forceinline__ void mma16816(float* d, const uint32_t* a,
                                         uint32_t b0, uint32_t b1) {
    asm volatile("mma.sync.aligned.m16n8k16.row.col.f32.f16.f16.f32 "
                 "{%0,%1,%2,%3}, {%4,%5,%6,%7}, {%8,%9}, {%0,%1,%2,%3};"
                 : "+f"(d[0]), "+f"(d[1]), "+f"(d[2]), "+f"(d[3])
                 : "r"(a[0]), "r"(a[1]), "r"(a[2]), "r"(a[3]), "r"(b0), "r"(b1));
}
__device__ __forceinline__ unsigned f2ord(float f) {
    unsigned u = __float_as_uint(f);
    return (u & 0x80000000u) ? ~u : (u | 0x80000000u);
}
__device__ __forceinline__ float ord2f(unsigned o) {
    unsigned u = (o & 0x80000000u) ? (o & 0x7FFFFFFFu) : ~o;
    return __uint_as_float(u);
}

// ------------- launch #1: normalize + fp16 hi/lo split (merged) ------------
// A rows: [hi|lo]; B rows: [hi|hi]  =>  C = hi.hi + lo.hi  (err ~1e-5)
__global__ __launch_bounds__(128)
void conv_all_kernel(const float* __restrict__ sk, const float* __restrict__ sq,
                     const float* __restrict__ q)
{
    int blk = blockIdx.x, t = threadIdx.x;
    const float* src;
    __half* d;
    int isA;
    if (blk < MPAD) {
        d = g_A + (size_t)blk * KT; isA = 1;
        src = (blk < LS) ? sk + (size_t)blk * D : nullptr;
    } else {
        int j = blk - MPAD;
        d = g_B + (size_t)j * KT; isA = 0;
        if (j < LS)        src = sq + (size_t)j * D;
        else if (j < NTOT) src = q + (size_t)(j - LS) * D;
        else               src = nullptr;
    }
    if (!src) {
        __half z = __float2half(0.f);
        for (int i = t; i < KT; i += 128) d[i] = z;
        return;
    }
    float ss = 0.f;
    for (int i = t; i < D; i += 128) { float x = src[i]; ss += x * x; }
    __shared__ float sh[4];
    for (int o = 16; o; o >>= 1) ss += __shfl_down_sync(0xffffffffu, ss, o);
    if ((t & 31) == 0) sh[t >> 5] = ss;
    __syncthreads();
    float scale = 1.0f / fmaxf(sqrtf(sh[0] + sh[1] + sh[2] + sh[3]), 1e-8f);
    for (int i = t; i < D; i += 128) {
        float x = src[i] * scale;
        __half h = __float2half(x);
        d[i] = h;
        d[D + i] = isA ? __float2half(x - __half2float(h)) : h;
    }
}

// ------------------- launch #2: zero E tables (merged) ---------------------
__global__ void fill_all_kernel()
{
    int i = blockIdx.x * blockDim.x + threadIdx.x;
    if (i < NSUP * LS) g_E1t[i] = 0.f;
    int j = i - NSUP * LS;
    if (j >= 0 && j < NQRY * LS) g_E2t[j] = 0.f;
}

// ---------------- launch #3: zero optimizer scratch (tiny) -----------------
__global__ void zero_scratch_kernel()
{
    int i = threadIdx.x;
    for (int k = i; k < 2 * OPT_STEPS + 1; k += 256) g_bar[k] = 0u;
    for (int k = i; k < (OPT_STEPS + 1) * NWAY; k += 256) g_gmax[k] = 0u;
    for (int k = i; k < OPT_STEPS * NSUP * NWAY; k += 256) g_gS[k] = 0.f;
}

// ------------- launch #4: HMMA GEMM 128x256, 3-stage pipeline --------------
// 512 threads, 16 warps (2M x 8N), warp tile 64x32, K chunks of 64 fp16.
// smem: A bufs 0/16K/32K (48K), B bufs 48K/80K/112K (96K). Total 144K.
#define SMB_B    49152
#define SM_TOTAL 147456

__device__ __forceinline__ void ep_flush(int seg, float sum, int r)
{
    if (seg < NSUP) atomicAdd(&g_E1t[seg * LS + r], sum);
    else            atomicAdd(&g_E2t[(seg - NSUP) * LS + r], sum);
}

__global__ __launch_bounds__(512, 1)
void gemm_kernel(const __half* __restrict__ A, const __half* __restrict__ B)
{
    extern __shared__ char smem[];
    uint32_t sb = smem_u32(smem);
    int tid = threadIdx.x, wid = tid >> 5, lane = tid & 31;
    int row0 = blockIdx.y * 128;
    int col0 = blockIdx.x * 256;
    int wm = wid & 1, wn = wid >> 1;

    int arow = tid >> 2, aseg = (tid & 3) * 2;
    int brow = tid >> 1, bseg = (tid & 1) * 4;
    const __half* asrc = A + (size_t)(row0 + arow) * KT + aseg * 8;
    const __half* bsrc = B + (size_t)(col0 + brow) * KT + bseg * 8;
    uint32_t adsto = arow * 128 + aseg * 16;
    uint32_t bdsto = brow * 128 + bseg * 16;

#define LOAD_CHUNK(c, buf) do {                                               \
        uint32_t _ab = sb + (buf) * 16384;                                    \
        uint32_t _bb = sb + SMB_B + (buf) * 32768;                            \
        const __half* _as = asrc + (c) * 64;                                  \
        const __half* _bs = bsrc + (c) * 64;                                  \
        CP16(_ab + SWZ(adsto),      _as);                                     \
        CP16(_ab + SWZ(adsto + 16), _as + 8);                                 \
        CP16(_bb + SWZ(bdsto),      _bs);                                     \
        CP16(_bb + SWZ(bdsto + 16), _bs + 8);                                 \
        CP16(_bb + SWZ(bdsto + 32), _bs + 16);                                \
        CP16(_bb + SWZ(bdsto + 48), _bs + 24);                                \
        CP_COMMIT(); } while (0)

    float acc[4][4][4];
#pragma unroll
    for (int i = 0; i < 4; i++)
#pragma unroll
        for (int j = 0; j < 4; j++)
#pragma unroll
            for (int k = 0; k < 4; k++) acc[i][j][k] = 0.f;

    LOAD_CHUNK(0, 0);
    LOAD_CHUNK(1, 1);

    int a_row = wm * 64 + (lane & 15);
    int a_kb  = (lane >> 4) * 16;
    int b_row = wn * 32 + (lane & 7) + ((lane >> 4) << 3);
    int b_kb  = ((lane >> 3) & 1) * 16;

    int buf = 0, nbuf = 2;
    for (int c = 0; c < NCHUNK; c++) {
        CP_WAIT1();                 // this chunk's data landed (1 grp in flight)
        __syncthreads();            // all threads' data in; buf (c+2)%3 free
        if (c + 2 < NCHUNK) LOAD_CHUNK(c + 2, nbuf);   // overlaps compute
        uint32_t ab = sb + buf * 16384;
        uint32_t bb = sb + SMB_B + buf * 32768;
#pragma unroll
        for (int ks = 0; ks < 4; ks++) {
            int kb = ks * 32;
            uint32_t areg[4][4], breg[2][4];
#pragma unroll
            for (int mi = 0; mi < 4; mi++)
                ldmx4(areg[mi], ab + SWZ((a_row + mi * 16) * 128 + a_kb + kb));
#pragma unroll
            for (int nh = 0; nh < 2; nh++)
                ldmx4(breg[nh], bb + SWZ((b_row + nh * 16) * 128 + b_kb + kb));
#pragma unroll
            for (int mi = 0; mi < 4; mi++)
#pragma unroll
                for (int ni = 0; ni < 4; ni++)
                    mma16816(acc[mi][ni], areg[mi],
                             breg[ni >> 1][(ni & 1) * 2],
                             breg[ni >> 1][(ni & 1) * 2 + 1]);
        }
        buf = (buf + 1) % 3; nbuf = (nbuf + 1) % 3;
    }

    // epilogue: exp + per-image segment sums + atomics
    int colT = col0 + wn * 32;
    if (colT >= NTOT) return;
    int segA = colT / SEQ;
    int bcol = (segA + 1) * SEQ - colT;
    if (bcol > 32) bcol = 32;
    int segB = segA + 1;
    int cbase = (lane & 3) * 2;

#pragma unroll
    for (int mi = 0; mi < 4; mi++) {
#pragma unroll
        for (int half = 0; half < 2; half++) {
            int r = row0 + wm * 64 + mi * 16 + (lane >> 2) + half * 8;
            float sumA = 0.f, sumB = 0.f;
#pragma unroll
            for (int ni = 0; ni < 4; ni++) {
#pragma unroll
                for (int j = 0; j < 2; j++) {
                    int coff = ni * 8 + cbase + j;
                    float e = exp2f(acc[mi][ni][half * 2 + j] * SCALE2);
                    if (coff < bcol) sumA += e; else sumB += e;
                }
            }
            sumA += __shfl_xor_sync(0xffffffffu, sumA, 1);
            sumA += __shfl_xor_sync(0xffffffffu, sumA, 2);
            sumB += __shfl_xor_sync(0xffffffffu, sumB, 1);
            sumB += __shfl_xor_sync(0xffffffffu, sumB, 2);
            if ((lane & 3) == 0 && r < LS) {
                int rimg = r / SEQ;
                if (segA != rimg)
                    ep_flush(segA, sumA, r);
                if (bcol < 32 && segB < NSEG && segB != rimg)
                    ep_flush(segB, sumB, r);
            }
        }
    }
}

// ------------- launch #5: optimizer, 25 CTAs + grid barriers ---------------
__device__ __forceinline__ void gridbar(int i)
{
    __syncthreads();
    if (threadIdx.x == 0) {
        __threadfence();
        unsigned o = atomicAdd(&g_bar[i], 1u);
        if (o + 1 < NOPT) {
            while (atomicAdd(&g_bar[i], 0u) < NOPT) __nanosleep(64);
        }
        __threadfence();
    }
    __syncthreads();
}

__global__ __launch_bounds__(256, 1)
void optimize_kernel(const int* __restrict__ labels)
{
    __shared__ float Esl[NSUP][SEQ];
    __shared__ float vsl[SEQ], sesl[SEQ];
    __shared__ float cb[NSUP];
    __shared__ float red[8];

    int img = blockIdx.x;
    int w = img / 5;
    int tid = threadIdx.x, warp = tid >> 5, lane = tid & 31;

    for (int b = 0; b < NSUP; b++)
        for (int t = tid; t < SEQ; t += 256)
            Esl[b][t] = g_E1t[b * LS + img * SEQ + t];
    for (int t = tid; t < SEQ; t += 256) vsl[t] = 0.f;
    __syncthreads();

    for (int step = 0; step < OPT_STEPS; ++step) {
        float m = -3.0e38f;
        for (int t = tid; t < SEQ; t += 256) m = fmaxf(m, vsl[t]);
        for (int o = 16; o; o >>= 1)
            m = fmaxf(m, __shfl_xor_sync(0xffffffffu, m, o));
        if (lane == 0) red[warp] = m;
        __syncthreads();
        if (tid == 0) {
            float mm = red[0];
            for (int u = 1; u < 8; u++) mm = fmaxf(mm, red[u]);
            atomicMax(&g_gmax[step * NWAY + w], f2ord(mm));
        }
        gridbar(2 * step);

        float mx = ord2f(g_gmax[step * NWAY + w]);
        for (int t = tid; t < SEQ; t += 256)
            sesl[t] = __expf((vsl[t] - mx) * INVT);
        __syncthreads();
        for (int b = warp; b < NSUP; b += 8) {
            float s = 0.f;
            for (int t = lane; t < SEQ; t += 32) s += sesl[t] * Esl[b][t];
            for (int o = 16; o; o >>= 1) s += __shfl_down_sync(0xffffffffu, s, o);
            if (lane == 0) atomicAdd(&g_gS[step * 125 + b * NWAY + w], s);
        }
        gridbar(2 * step + 1);

        if (tid < NSUP) {
            int b = tid;
            float p[NWAY], mm = -3.0e38f;
            for (int wp = 0; wp < NWAY; wp++) {
                p[wp] = logf(g_gS[step * 125 + b * NWAY + wp]) +
                        ord2f(g_gmax[step * NWAY + wp]) * INVT;
                mm = fmaxf(mm, p[wp]);
            }
            float ex[NWAY], se = 0.f;
            for (int wp = 0; wp < NWAY; wp++) { ex[wp] = __expf(p[wp] - mm); se += ex[wp]; }
            int lab = labels[b];
            float coef = (ex[w] / se - (w == lab ? 1.f : 0.f)) / (float)NSUP;
            cb[b] = coef / g_gS[step * 125 + b * NWAY + w];
        }
        __syncthreads();
        for (int t = tid; t < SEQ; t += 256) {
            float g = 0.f;
#pragma unroll
            for (int b = 0; b < NSUP; b++) g += cb[b] * Esl[b][t];
            vsl[t] -= LRATE * INVT * sesl[t] * g;
        }
        __syncthreads();
    }

    {
        float m = -3.0e38f;
        for (int t = tid; t < SEQ; t += 256) m = fmaxf(m, vsl[t]);
        for (int o = 16; o; o >>= 1)
            m = fmaxf(m, __shfl_xor_sync(0xffffffffu, m, o));
        if (lane == 0) red[warp] = m;
        __syncthreads();
        if (tid == 0) {
            float mm = red[0];
            for (int u = 1; u < 8; u++) mm = fmaxf(mm, red[u]);
            atomicMax(&g_gmax[OPT_STEPS * NWAY + w], f2ord(mm));
        }
        gridbar(2 * OPT_STEPS);
        float mx = ord2f(g_gmax[OPT_STEPS * NWAY + w]);
        for (int t = tid; t < SEQ; t += 256)
            g_e[img * SEQ + t] = __expf((vsl[t] - mx) * INVT);
        if (tid == 0) g_mxc[w] = mx * INVT;
    }
}

// --------------------------- launch #6: final LSE --------------------------
__global__ __launch_bounds__(128)
void final_kernel(float* __restrict__ out)
{
    int pair = blockIdx.x;
    int b = pair / NWAY, w = pair % NWAY;
    int base = w * PER_W;
    int tid = threadIdx.x;
    float s = 0.f;
    for (int idx = tid; idx < PER_W; idx += 128)
        s += g_e[base + idx] * g_E2t[b * LS + base + idx];
    __shared__ float sh[4];
    for (int o = 16; o; o >>= 1) s += __shfl_down_sync(0xffffffffu, s, o);
    if ((tid & 31) == 0) sh[tid >> 5] = s;
    __syncthreads();
    if (tid == 0)
        out[pair] = logf(sh[0] + sh[1] + sh[2] + sh[3]) + g_mxc[w];
}

// ---------------------------------------------------------------------------
extern "C" void kernel_launch(void* const* d_in, const int* in_sizes, int n_in,
                              void* d_out, int out_size)
{
    const float* sk  = (const float*)d_in[0];
    const float* sq  = (const float*)d_in[1];
    const float* q   = (const float*)d_in[2];
    const int*   lab = (const int*)  d_in[3];
    float*       out = (float*)d_out;

    __half *A, *B;
    cudaGetSymbolAddress((void**)&A, g_A);
    cudaGetSymbolAddress((void**)&B, g_B);

    cudaFuncSetAttribute(gemm_kernel,
                         cudaFuncAttributeMaxDynamicSharedMemorySize, SM_TOTAL);

    conv_all_kernel<<<MPAD + NPAD, 128>>>(sk, sq, q);                  // #1
    fill_all_kernel<<<((NSUP + NQRY) * LS + 255) / 256, 256>>>();      // #2
    zero_scratch_kernel<<<1, 256>>>();                                 // #3
    dim3 grid(NPAD / 256, MPAD / 128);
    gemm_kernel<<<grid, 512, SM_TOTAL>>>(A, B);                        // #4
    optimize_kernel<<<NOPT, 256>>>(lab);                               // #5
    final_kernel<<<NQRY * NWAY, 128>>>(out);                           // #6
}

// round 12
// speedup vs baseline: 6.3858x; 1.5290x over previous
#include <cuda_runtime.h>
#include <cuda_fp16.h>
#include <cstdint>
#include <math.h>

#define D       384
#define SEQ     196
#define NWAY    5
#define NSUP    25
#define NQRY    75
#define LS      4900
#define PER_W   980
#define KT      384           // pure fp16, no split
#define NCHUNK  6             // KT / 64
#define MPAD    4992          // 39*128
#define NTOT    19600         // 4900 + 14700
#define NPAD    19712         // 77*256
#define NSEG    100
#define OPT_STEPS 15
#define NOPT    25
#define LRATE   0.1f
#define INVT    (1.0f/0.0510310363f)
#define SCALE2  (INVT * 1.4426950408889634f)

static __device__ __align__(16) __half g_A[MPAD * KT];
static __device__ __align__(16) __half g_B[NPAD * KT];
static __device__ float g_E1t[NSUP * LS];   // [b][sp] raw exp-sums (masked)
static __device__ float g_E2t[NQRY * LS];   // [b][sp]
static __device__ float g_e[LS];
static __device__ float g_mxc[NWAY];
static __device__ unsigned g_bar[2 * OPT_STEPS + 1];
static __device__ unsigned g_gmax[(OPT_STEPS + 1) * NWAY];
static __device__ float    g_gS[OPT_STEPS * NSUP * NWAY];

__device__ __forceinline__ uint32_t smem_u32(const void* p) {
    uint32_t a;
    asm("{ .reg .u64 t; cvta.to.shared.u64 t, %1; cvt.u32.u64 %0, t; }"
        : "=r"(a) : "l"(p));
    return a;
}
#define SWZ(o) ((o) ^ (((o) >> 3) & 0x70))
#define CP16(dst, src)  asm volatile("cp.async.cg.shared.global [%0], [%1], 16;" :: "r"(dst), "l"(src))
#define CP_COMMIT()     asm volatile("cp.async.commit_group;" ::: "memory")
#define CP_WAIT1()      asm volatile("cp.async.wait_group 1;" ::: "memory")

__device__ __forceinline__ void ldmx4(uint32_t* r, uint32_t addr) {
    asm volatile("ldmatrix.sync.aligned.m8n8.x4.shared.b16 {%0,%1,%2,%3}, [%4];"
                 : "=r"(r[0]), "=r"(r[1]), "=r"(r[2]), "=r"(r[3]) : "r"(addr));
}
__device__ __forceinline__ void mma16816(float* d, const uint32_t* a,
                                         uint32_t b0, uint32_t b1) {
    asm volatile("mma.sync.aligned.m16n8k16.row.col.f32.f16.f16.f32 "
                 "{%0,%1,%2,%3}, {%4,%5,%6,%7}, {%8,%9}, {%0,%1,%2,%3};"
                 : "+f"(d[0]), "+f"(d[1]), "+f"(d[2]), "+f"(d[3])
                 : "r"(a[0]), "r"(a[1]), "r"(a[2]), "r"(a[3]), "r"(b0), "r"(b1));
}
__device__ __forceinline__ unsigned f2ord(float f) {
    unsigned u = __float_as_uint(f);
    return (u & 0x80000000u) ? ~u : (u | 0x80000000u);
}
__device__ __forceinline__ float ord2f(unsigned o) {
    unsigned u = (o & 0x80000000u) ? (o & 0x7FFFFFFFu) : ~o;
    return __uint_as_float(u);
}

// ------------- launch #1: normalize + fp16 convert (merged) ----------------
__global__ __launch_bounds__(128)
void conv_all_kernel(const float* __restrict__ sk, const float* __restrict__ sq,
                     const float* __restrict__ q)
{
    int blk = blockIdx.x, t = threadIdx.x;
    const float* src;
    __half* d;
    if (blk < MPAD) {
        d = g_A + (size_t)blk * KT;
        src = (blk < LS) ? sk + (size_t)blk * D : nullptr;
    } else {
        int j = blk - MPAD;
        d = g_B + (size_t)j * KT;
        if (j < LS)        src = sq + (size_t)j * D;
        else if (j < NTOT) src = q + (size_t)(j - LS) * D;
        else               src = nullptr;
    }
    if (!src) {
        __half z = __float2half(0.f);
        for (int i = t; i < KT; i += 128) d[i] = z;
        return;
    }
    float ss = 0.f;
    for (int i = t; i < D; i += 128) { float x = src[i]; ss += x * x; }
    __shared__ float sh[4];
    for (int o = 16; o; o >>= 1) ss += __shfl_down_sync(0xffffffffu, ss, o);
    if ((t & 31) == 0) sh[t >> 5] = ss;
    __syncthreads();
    float scale = 1.0f / fmaxf(sqrtf(sh[0] + sh[1] + sh[2] + sh[3]), 1e-8f);
    for (int i = t; i < D; i += 128)
        d[i] = __float2half(src[i] * scale);
}

// ------------------- launch #2: zero E tables (merged) ---------------------
__global__ void fill_all_kernel()
{
    int i = blockIdx.x * blockDim.x + threadIdx.x;
    if (i < NSUP * LS) g_E1t[i] = 0.f;
    int j = i - NSUP * LS;
    if (j >= 0 && j < NQRY * LS) g_E2t[j] = 0.f;
}

// ---------------- launch #3: zero optimizer scratch (tiny) -----------------
__global__ void zero_scratch_kernel()
{
    int i = threadIdx.x;
    for (int k = i; k < 2 * OPT_STEPS + 1; k += 256) g_bar[k] = 0u;
    for (int k = i; k < (OPT_STEPS + 1) * NWAY; k += 256) g_gmax[k] = 0u;
    for (int k = i; k < OPT_STEPS * NSUP * NWAY; k += 256) g_gS[k] = 0.f;
}

// ------------- launch #4: HMMA GEMM 128x256, 3-stage pipeline --------------
// 512 threads, 16 warps (2M x 8N), warp tile 64x32, K chunks of 64 fp16.
// smem: A bufs 0/16K/32K (48K), B bufs 48K/80K/112K (96K). Total 144K.
#define SMB_B    49152
#define SM_TOTAL 147456

__device__ __forceinline__ void ep_flush(int seg, float sum, int r)
{
    if (seg < NSUP) atomicAdd(&g_E1t[seg * LS + r], sum);
    else            atomicAdd(&g_E2t[(seg - NSUP) * LS + r], sum);
}

__global__ __launch_bounds__(512, 1)
void gemm_kernel(const __half* __restrict__ A, const __half* __restrict__ B)
{
    extern __shared__ char smem[];
    uint32_t sb = smem_u32(smem);
    int tid = threadIdx.x, wid = tid >> 5, lane = tid & 31;
    int row0 = blockIdx.y * 128;
    int col0 = blockIdx.x * 256;
    int wm = wid & 1, wn = wid >> 1;

    int arow = tid >> 2, aseg = (tid & 3) * 2;
    int brow = tid >> 1, bseg = (tid & 1) * 4;
    const __half* asrc = A + (size_t)(row0 + arow) * KT + aseg * 8;
    const __half* bsrc = B + (size_t)(col0 + brow) * KT + bseg * 8;
    uint32_t adsto = arow * 128 + aseg * 16;
    uint32_t bdsto = brow * 128 + bseg * 16;

#define LOAD_CHUNK(c, buf) do {                                               \
        uint32_t _ab = sb + (buf) * 16384;                                    \
        uint32_t _bb = sb + SMB_B + (buf) * 32768;                            \
        const __half* _as = asrc + (c) * 64;                                  \
        const __half* _bs = bsrc + (c) * 64;                                  \
        CP16(_ab + SWZ(adsto),      _as);                                     \
        CP16(_ab + SWZ(adsto + 16), _as + 8);                                 \
        CP16(_bb + SWZ(bdsto),      _bs);                                     \
        CP16(_bb + SWZ(bdsto + 16), _bs + 8);                                 \
        CP16(_bb + SWZ(bdsto + 32), _bs + 16);                                \
        CP16(_bb + SWZ(bdsto + 48), _bs + 24);                                \
        CP_COMMIT(); } while (0)

    float acc[4][4][4];
#pragma unroll
    for (int i = 0; i < 4; i++)
#pragma unroll
        for (int j = 0; j < 4; j++)
#pragma unroll
            for (int k = 0; k < 4; k++) acc[i][j][k] = 0.f;

    LOAD_CHUNK(0, 0);
    LOAD_CHUNK(1, 1);

    int a_row = wm * 64 + (lane & 15);
    int a_kb  = (lane >> 4) * 16;
    int b_row = wn * 32 + (lane & 7) + ((lane >> 4) << 3);
    int b_kb  = ((lane >> 3) & 1) * 16;

    int buf = 0, nbuf = 2;
    for (int c = 0; c < NCHUNK; c++) {
        CP_WAIT1();                 // uniform group count => chunk c landed
        __syncthreads();
        // always commit a group (empty near the tail) so wait_group 1 is exact
        if (c + 2 < NCHUNK) LOAD_CHUNK(c + 2, nbuf);
        else                CP_COMMIT();
        uint32_t ab = sb + buf * 16384;
        uint32_t bb = sb + SMB_B + buf * 32768;
#pragma unroll
        for (int ks = 0; ks < 4; ks++) {
            int kb = ks * 32;
            uint32_t areg[4][4], breg[2][4];
#pragma unroll
            for (int mi = 0; mi < 4; mi++)
                ldmx4(areg[mi], ab + SWZ((a_row + mi * 16) * 128 + a_kb + kb));
#pragma unroll
            for (int nh = 0; nh < 2; nh++)
                ldmx4(breg[nh], bb + SWZ((b_row + nh * 16) * 128 + b_kb + kb));
#pragma unroll
            for (int mi = 0; mi < 4; mi++)
#pragma unroll
                for (int ni = 0; ni < 4; ni++)
                    mma16816(acc[mi][ni], areg[mi],
                             breg[ni >> 1][(ni & 1) * 2],
                             breg[ni >> 1][(ni & 1) * 2 + 1]);
        }
        buf = (buf + 1) % 3; nbuf = (nbuf + 1) % 3;
    }

    // epilogue: exp + per-image segment sums + atomics
    int colT = col0 + wn * 32;
    if (colT >= NTOT) return;
    int segA = colT / SEQ;
    int bcol = (segA + 1) * SEQ - colT;
    if (bcol > 32) bcol = 32;
    int segB = segA + 1;
    int cbase = (lane & 3) * 2;

#pragma unroll
    for (int mi = 0; mi < 4; mi++) {
#pragma unroll
        for (int half = 0; half < 2; half++) {
            int r = row0 + wm * 64 + mi * 16 + (lane >> 2) + half * 8;
            float sumA = 0.f, sumB = 0.f;
#pragma unroll
            for (int ni = 0; ni < 4; ni++) {
#pragma unroll
                for (int j = 0; j < 2; j++) {
                    int coff = ni * 8 + cbase + j;
                    float e = exp2f(acc[mi][ni][half * 2 + j] * SCALE2);
                    if (coff < bcol) sumA += e; else sumB += e;
                }
            }
            sumA += __shfl_xor_sync(0xffffffffu, sumA, 1);
            sumA += __shfl_xor_sync(0xffffffffu, sumA, 2);
            sumB += __shfl_xor_sync(0xffffffffu, sumB, 1);
            sumB += __shfl_xor_sync(0xffffffffu, sumB, 2);
            if ((lane & 3) == 0 && r < LS) {
                int rimg = r / SEQ;
                if (segA != rimg)
                    ep_flush(segA, sumA, r);
                if (bcol < 32 && segB < NSEG && segB != rimg)
                    ep_flush(segB, sumB, r);
            }
        }
    }
}

// ------------- launch #5: optimizer, 25 CTAs + grid barriers ---------------
__device__ __forceinline__ void gridbar(int i)
{
    __syncthreads();
    if (threadIdx.x == 0) {
        __threadfence();
        unsigned o = atomicAdd(&g_bar[i], 1u);
        if (o + 1 < NOPT) {
            while (atomicAdd(&g_bar[i], 0u) < NOPT) __nanosleep(64);
        }
        __threadfence();
    }
    __syncthreads();
}

__global__ __launch_bounds__(256, 1)
void optimize_kernel(const int* __restrict__ labels)
{
    __shared__ float Esl[NSUP][SEQ];
    __shared__ float vsl[SEQ], sesl[SEQ];
    __shared__ float cb[NSUP];
    __shared__ float red[8];

    int img = blockIdx.x;
    int w = img / 5;
    int tid = threadIdx.x, warp = tid >> 5, lane = tid & 31;

    for (int b = 0; b < NSUP; b++)
        for (int t = tid; t < SEQ; t += 256)
            Esl[b][t] = g_E1t[b * LS + img * SEQ + t];
    for (int t = tid; t < SEQ; t += 256) vsl[t] = 0.f;
    __syncthreads();

    for (int step = 0; step < OPT_STEPS; ++step) {
        float m = -3.0e38f;
        for (int t = tid; t < SEQ; t += 256) m = fmaxf(m, vsl[t]);
        for (int o = 16; o; o >>= 1)
            m = fmaxf(m, __shfl_xor_sync(0xffffffffu, m, o));
        if (lane == 0) red[warp] = m;
        __syncthreads();
        if (tid == 0) {
            float mm = red[0];
            for (int u = 1; u < 8; u++) mm = fmaxf(mm, red[u]);
            atomicMax(&g_gmax[step * NWAY + w], f2ord(mm));
        }
        gridbar(2 * step);

        float mx = ord2f(g_gmax[step * NWAY + w]);
        for (int t = tid; t < SEQ; t += 256)
            sesl[t] = __expf((vsl[t] - mx) * INVT);
        __syncthreads();
        for (int b = warp; b < NSUP; b += 8) {
            float s = 0.f;
            for (int t = lane; t < SEQ; t += 32) s += sesl[t] * Esl[b][t];
            for (int o = 16; o; o >>= 1) s += __shfl_down_sync(0xffffffffu, s, o);
            if (lane == 0) atomicAdd(&g_gS[step * 125 + b * NWAY + w], s);
        }
        gridbar(2 * step + 1);

        if (tid < NSUP) {
            int b = tid;
            float p[NWAY], mm = -3.0e38f;
            for (int wp = 0; wp < NWAY; wp++) {
                p[wp] = logf(g_gS[step * 125 + b * NWAY + wp]) +
                        ord2f(g_gmax[step * NWAY + wp]) * INVT;
                mm = fmaxf(mm, p[wp]);
            }
            float ex[NWAY], se = 0.f;
            for (int wp = 0; wp < NWAY; wp++) { ex[wp] = __expf(p[wp] - mm); se += ex[wp]; }
            int lab = labels[b];
            float coef = (ex[w] / se - (w == lab ? 1.f : 0.f)) / (float)NSUP;
            cb[b] = coef / g_gS[step * 125 + b * NWAY + w];
        }
        __syncthreads();
        for (int t = tid; t < SEQ; t += 256) {
            float g = 0.f;
#pragma unroll
            for (int b = 0; b < NSUP; b++) g += cb[b] * Esl[b][t];
            vsl[t] -= LRATE * INVT * sesl[t] * g;
        }
        __syncthreads();
    }

    {
        float m = -3.0e38f;
        for (int t = tid; t < SEQ; t += 256) m = fmaxf(m, vsl[t]);
        for (int o = 16; o; o >>= 1)
            m = fmaxf(m, __shfl_xor_sync(0xffffffffu, m, o));
        if (lane == 0) red[warp] = m;
        __syncthreads();
        if (tid == 0) {
            float mm = red[0];
            for (int u = 1; u < 8; u++) mm = fmaxf(mm, red[u]);
            atomicMax(&g_gmax[OPT_STEPS * NWAY + w], f2ord(mm));
        }
        gridbar(2 * OPT_STEPS);
        float mx = ord2f(g_gmax[OPT_STEPS * NWAY + w]);
        for (int t = tid; t < SEQ; t += 256)
            g_e[img * SEQ + t] = __expf((vsl[t] - mx) * INVT);
        if (tid == 0) g_mxc[w] = mx * INVT;
    }
}

// --------------------------- launch #6: final LSE --------------------------
__global__ __launch_bounds__(128)
void final_kernel(float* __restrict__ out)
{
    int pair = blockIdx.x;
    int b = pair / NWAY, w = pair % NWAY;
    int base = w * PER_W;
    int tid = threadIdx.x;
    float s = 0.f;
    for (int idx = tid; idx < PER_W; idx += 128)
        s += g_e[base + idx] * g_E2t[b * LS + base + idx];
    __shared__ float sh[4];
    for (int o = 16; o; o >>= 1) s += __shfl_down_sync(0xffffffffu, s, o);
    if ((tid & 31) == 0) sh[tid >> 5] = s;
    __syncthreads();
    if (tid == 0)
        out[pair] = logf(sh[0] + sh[1] + sh[2] + sh[3]) + g_mxc[w];
}

// ---------------------------------------------------------------------------
extern "C" void kernel_launch(void* const* d_in, const int* in_sizes, int n_in,
                              void* d_out, int out_size)
{
    const float* sk  = (const float*)d_in[0];
    const float* sq  = (const float*)d_in[1];
    const float* q   = (const float*)d_in[2];
    const int*   lab = (const int*)  d_in[3];
    float*       out = (float*)d_out;

    __half *A, *B;
    cudaGetSymbolAddress((void**)&A, g_A);
    cudaGetSymbolAddress((void**)&B, g_B);

    cudaFuncSetAttribute(gemm_kernel,
                         cudaFuncAttributeMaxDynamicSharedMemorySize, SM_TOTAL);

    conv_all_kernel<<<MPAD + NPAD, 128>>>(sk, sq, q);                  // #1
    fill_all_kernel<<<((NSUP + NQRY) * LS + 255) / 256, 256>>>();      // #2
    zero_scratch_kernel<<<1, 256>>>();                                 // #3
    dim3 grid(NPAD / 256, MPAD / 128);
    gemm_kernel<<<grid, 512, SM_TOTAL>>>(A, B);                        // #4
    optimize_kernel<<<NOPT, 256>>>(lab);                               // #5
    final_kernel<<<NQRY * NWAY, 128>>>(out);                           // #6
}

// round 17
// speedup vs baseline: 6.7957x; 1.0642x over previous
#include <cuda_runtime.h>
#include <cuda_fp16.h>
#include <cstdint>
#include <math.h>

#define D       384
#define SEQ     196
#define NWAY    5
#define NSUP    25
#define NQRY    75
#define LS      4900
#define PER_W   980
#define KT      384           // pure fp16
#define NCHUNK  6             // KT / 64
#define MPAD    4992          // 39*128
#define NTOT    19600         // 4900 + 14700
#define NPAD    19712         // 154*128
#define NSEG    100
#define OPT_STEPS 15
#define NOPT    5             // optimizer CTAs (one per class)
#define LRATE   0.1f
#define INVT    (1.0f/0.0510310363f)
#define SCALE2  (INVT * 1.4426950408889634f)

static __device__ __align__(16) __half g_A[MPAD * KT];
static __device__ __align__(16) __half g_B[NPAD * KT];
static __device__ float g_E1t[NSUP * LS];   // [b][sp] raw exp-sums (masked)
static __device__ float g_E2t[NQRY * LS];   // [b][sp]
static __device__ float g_e[LS];
static __device__ float g_mxc[NWAY];
static __device__ unsigned g_bar[OPT_STEPS];            // spin barriers
static __device__ float    g_gmaxS[OPT_STEPS * NWAY];   // per-step class ref
static __device__ float    g_gS[OPT_STEPS * NSUP * NWAY];

__device__ __forceinline__ uint32_t smem_u32(const void* p) {
    uint32_t a;
    asm("{ .reg .u64 t; cvta.to.shared.u64 t, %1; cvt.u32.u64 %0, t; }"
        : "=r"(a) : "l"(p));
    return a;
}
#define SWZ(o) ((o) ^ (((o) >> 3) & 0x70))
#define CP16(dst, src)  asm volatile("cp.async.cg.shared.global [%0], [%1], 16;" :: "r"(dst), "l"(src))
#define CP_COMMIT()     asm volatile("cp.async.commit_group;" ::: "memory")
#define CP_WAIT1()      asm volatile("cp.async.wait_group 1;" ::: "memory")

__device__ __forceinline__ void ldmx4(uint32_t* r, uint32_t addr) {
    asm volatile("ldmatrix.sync.aligned.m8n8.x4.shared.b16 {%0,%1,%2,%3}, [%4];"
                 : "=r"(r[0]), "=r"(r[1]), "=r"(r[2]), "=r"(r[3]) : "r"(addr));
}
__device__ __forceinline__ void mma16816(float* d, const uint32_t* a,
                                         uint32_t b0, uint32_t b1) {
    asm volatile("mma.sync.aligned.m16n8k16.row.col.f32.f16.f16.f32 "
                 "{%0,%1,%2,%3}, {%4,%5,%6,%7}, {%8,%9}, {%0,%1,%2,%3};"
                 : "+f"(d[0]), "+f"(d[1]), "+f"(d[2]), "+f"(d[3])
                 : "r"(a[0]), "r"(a[1]), "r"(a[2]), "r"(a[3]), "r"(b0), "r"(b1));
}

// ------------- launch #1: normalize + fp16 convert (merged) ----------------
__global__ __launch_bounds__(128)
void conv_all_kernel(const float* __restrict__ sk, const float* __restrict__ sq,
                     const float* __restrict__ q)
{
    int blk = blockIdx.x, t = threadIdx.x;
    const float* src;
    __half* d;
    if (blk < MPAD) {
        d = g_A + (size_t)blk * KT;
        src = (blk < LS) ? sk + (size_t)blk * D : nullptr;
    } else {
        int j = blk - MPAD;
        d = g_B + (size_t)j * KT;
        if (j < LS)        src = sq + (size_t)j * D;
        else if (j < NTOT) src = q + (size_t)(j - LS) * D;
        else               src = nullptr;
    }
    if (!src) {
        __half z = __float2half(0.f);
        for (int i = t; i < KT; i += 128) d[i] = z;
        return;
    }
    float ss = 0.f;
    for (int i = t; i < D; i += 128) { float x = src[i]; ss += x * x; }
    __shared__ float sh[4];
    for (int o = 16; o; o >>= 1) ss += __shfl_down_sync(0xffffffffu, ss, o);
    if ((t & 31) == 0) sh[t >> 5] = ss;
    __syncthreads();
    float scale = 1.0f / fmaxf(sqrtf(sh[0] + sh[1] + sh[2] + sh[3]), 1e-8f);
    for (int i = t; i < D; i += 128)
        d[i] = __float2half(src[i] * scale);
}

// ------------------- launch #2: zero E tables (merged) ---------------------
__global__ void fill_all_kernel()
{
    int i = blockIdx.x * blockDim.x + threadIdx.x;
    if (i < NSUP * LS) g_E1t[i] = 0.f;
    int j = i - NSUP * LS;
    if (j >= 0 && j < NQRY * LS) g_E2t[j] = 0.f;
}

// ---------------- launch #3: zero optimizer barriers (tiny) ----------------
__global__ void zero_scratch_kernel()
{
    int i = threadIdx.x;
    if (i < OPT_STEPS) g_bar[i] = 0u;
}

// -------- launch #4: HMMA GEMM 128x128, 256 thr, 2 CTA/SM, 3-stage ---------
// 8 warps (2M x 4N), warp tile 64x32, K chunks of 64 fp16.
// smem: A bufs 0/16K/32K, B bufs 48K/64K/80K. Total 96K per CTA.
#define SMB_B    49152
#define SM_TOTAL 98304

__device__ __forceinline__ void ep_flush(int seg, float sum, int r)
{
    if (seg < NSUP) atomicAdd(&g_E1t[seg * LS + r], sum);
    else            atomicAdd(&g_E2t[(seg - NSUP) * LS + r], sum);
}

__global__ __launch_bounds__(256, 2)
void gemm_kernel(const __half* __restrict__ A, const __half* __restrict__ B)
{
    extern __shared__ char smem[];
    uint32_t sb = smem_u32(smem);
    int tid = threadIdx.x, wid = tid >> 5, lane = tid & 31;
    int row0 = blockIdx.y * 128;
    int col0 = blockIdx.x * 128;
    int wm = wid & 1, wn = wid >> 1;

    // cp.async: 2 threads per row, 4x16B segs each, for both A and B
    int ldrow = tid >> 1, ldseg = (tid & 1) * 4;
    const __half* asrc = A + (size_t)(row0 + ldrow) * KT + ldseg * 8;
    const __half* bsrc = B + (size_t)(col0 + ldrow) * KT + ldseg * 8;
    uint32_t dsto = ldrow * 128 + ldseg * 16;

#define LOAD_CHUNK(c, buf) do {                                               \
        uint32_t _ab = sb + (buf) * 16384;                                    \
        uint32_t _bb = sb + SMB_B + (buf) * 16384;                            \
        const __half* _as = asrc + (c) * 64;                                  \
        const __half* _bs = bsrc + (c) * 64;                                  \
        CP16(_ab + SWZ(dsto),      _as);                                      \
        CP16(_ab + SWZ(dsto + 16), _as + 8);                                  \
        CP16(_ab + SWZ(dsto + 32), _as + 16);                                 \
        CP16(_ab + SWZ(dsto + 48), _as + 24);                                 \
        CP16(_bb + SWZ(dsto),      _bs);                                      \
        CP16(_bb + SWZ(dsto + 16), _bs + 8);                                  \
        CP16(_bb + SWZ(dsto + 32), _bs + 16);                                 \
        CP16(_bb + SWZ(dsto + 48), _bs + 24);                                 \
        CP_COMMIT(); } while (0)

    float acc[4][4][4];
#pragma unroll
    for (int i = 0; i < 4; i++)
#pragma unroll
        for (int j = 0; j < 4; j++)
#pragma unroll
            for (int k = 0; k < 4; k++) acc[i][j][k] = 0.f;

    LOAD_CHUNK(0, 0);
    LOAD_CHUNK(1, 1);

    int a_row = wm * 64 + (lane & 15);
    int a_kb  = (lane >> 4) * 16;
    int b_row = wn * 32 + (lane & 7) + ((lane >> 4) << 3);
    int b_kb  = ((lane >> 3) & 1) * 16;

    int buf = 0, nbuf = 2;
    for (int c = 0; c < NCHUNK; c++) {
        CP_WAIT1();                 // uniform group count => chunk c landed
        __syncthreads();
        if (c + 2 < NCHUNK) LOAD_CHUNK(c + 2, nbuf);
        else                CP_COMMIT();        // keep group count uniform
        uint32_t ab = sb + buf * 16384;
        uint32_t bb = sb + SMB_B + buf * 16384;
#pragma unroll
        for (int ks = 0; ks < 4; ks++) {
            int kb = ks * 32;
            uint32_t areg[4][4], breg[2][4];
#pragma unroll
            for (int mi = 0; mi < 4; mi++)
                ldmx4(areg[mi], ab + SWZ((a_row + mi * 16) * 128 + a_kb + kb));
#pragma unroll
            for (int nh = 0; nh < 2; nh++)
                ldmx4(breg[nh], bb + SWZ((b_row + nh * 16) * 128 + b_kb + kb));
#pragma unroll
            for (int mi = 0; mi < 4; mi++)
#pragma unroll
                for (int ni = 0; ni < 4; ni++)
                    mma16816(acc[mi][ni], areg[mi],
                             breg[ni >> 1][(ni & 1) * 2],
                             breg[ni >> 1][(ni & 1) * 2 + 1]);
        }
        buf = (buf + 1) % 3; nbuf = (nbuf + 1) % 3;
    }

    // epilogue: exp + per-image segment sums + atomics
    int colT = col0 + wn * 32;
    if (colT >= NTOT) return;
    int segA = colT / SEQ;
    int bcol = (segA + 1) * SEQ - colT;
    if (bcol > 32) bcol = 32;
    int segB = segA + 1;
    int cbase = (lane & 3) * 2;

#pragma unroll
    for (int mi = 0; mi < 4; mi++) {
#pragma unroll
        for (int half = 0; half < 2; half++) {
            int r = row0 + wm * 64 + mi * 16 + (lane >> 2) + half * 8;
            float sumA = 0.f, sumB = 0.f;
#pragma unroll
            for (int ni = 0; ni < 4; ni++) {
#pragma unroll
                for (int j = 0; j < 2; j++) {
                    int coff = ni * 8 + cbase + j;
                    float e = exp2f(acc[mi][ni][half * 2 + j] * SCALE2);
                    if (coff < bcol) sumA += e; else sumB += e;
                }
            }
            sumA += __shfl_xor_sync(0xffffffffu, sumA, 1);
            sumA += __shfl_xor_sync(0xffffffffu, sumA, 2);
            sumB += __shfl_xor_sync(0xffffffffu, sumB, 1);
            sumB += __shfl_xor_sync(0xffffffffu, sumB, 2);
            if ((lane & 3) == 0 && r < LS) {
                int rimg = r / SEQ;
                if (segA != rimg)
                    ep_flush(segA, sumA, r);
                if (bcol < 32 && segB < NSEG && segB != rimg)
                    ep_flush(segB, sumB, r);
            }
        }
    }
}

// ------ launch #5: optimizer, 5 CTAs (one per class), 1 barrier/step -------
__device__ __forceinline__ void gridbar(int i)
{
    __syncthreads();
    if (threadIdx.x == 0) {
        __threadfence();
        unsigned o = atomicAdd(&g_bar[i], 1u);
        if (o + 1 < NOPT) {
            while (atomicAdd(&g_bar[i], 0u) < NOPT) __nanosleep(64);
        }
        __threadfence();
    }
    __syncthreads();
}

// dynamic smem: E[25][980] | vsl[980] | sesl[980]  (105840 B)
#define OPT_SMEM ((NSUP * PER_W + 2 * PER_W) * 4)

__global__ __launch_bounds__(512, 1)
void optimize_kernel(const int* __restrict__ labels)
{
    extern __shared__ float dsm[];
    float* E    = dsm;                       // [b*PER_W + t]
    float* vsl  = dsm + NSUP * PER_W;
    float* sesl = vsl + PER_W;
    __shared__ float cb[NSUP];
    __shared__ float red[16];
    __shared__ float mxs;

    int w = blockIdx.x;                      // class 0..4
    int base = w * PER_W;
    int tid = threadIdx.x, warp = tid >> 5, lane = tid & 31;

    for (int b = 0; b < NSUP; b++)
        for (int t = tid; t < PER_W; t += 512)
            E[b * PER_W + t] = g_E1t[b * LS + base + t];
    for (int t = tid; t < PER_W; t += 512) vsl[t] = 0.f;
    __syncthreads();

    for (int step = 0; step < OPT_STEPS; ++step) {
        // local class max (reference point; algebraically exact for any mx)
        float m = -3.0e38f;
        for (int t = tid; t < PER_W; t += 512) m = fmaxf(m, vsl[t]);
        for (int o = 16; o; o >>= 1)
            m = fmaxf(m, __shfl_xor_sync(0xffffffffu, m, o));
        if (lane == 0) red[warp] = m;
        __syncthreads();
        if (tid == 0) {
            float mm = red[0];
            for (int u = 1; u < 16; u++) mm = fmaxf(mm, red[u]);
            mxs = mm;
            g_gmaxS[step * NWAY + w] = mm;   // single writer
        }
        __syncthreads();
        float mx = mxs;
        for (int t = tid; t < PER_W; t += 512)
            sesl[t] = __expf((vsl[t] - mx) * INVT);
        __syncthreads();

        // S[b,w] = dot(se, E[b]); warp per b, single writer per slot
        for (int b = warp; b < NSUP; b += 16) {
            float s = 0.f;
            for (int t = lane; t < PER_W; t += 32)
                s += sesl[t] * E[b * PER_W + t];
            for (int o = 16; o; o >>= 1)
                s += __shfl_down_sync(0xffffffffu, s, o);
            if (lane == 0) g_gS[step * 125 + b * NWAY + w] = s;
        }
        gridbar(step);

        // per-b softmax coeff for our class
        if (tid < NSUP) {
            int b = tid;
            float p[NWAY], mm = -3.0e38f;
            for (int wp = 0; wp < NWAY; wp++) {
                p[wp] = logf(g_gS[step * 125 + b * NWAY + wp]) +
                        g_gmaxS[step * NWAY + wp] * INVT;
                mm = fmaxf(mm, p[wp]);
            }
            float ex[NWAY], se = 0.f;
            for (int wp = 0; wp < NWAY; wp++) { ex[wp] = __expf(p[wp] - mm); se += ex[wp]; }
            int lab = labels[b];
            float coef = (ex[w] / se - (w == lab ? 1.f : 0.f)) / (float)NSUP;
            cb[b] = coef / g_gS[step * 125 + b * NWAY + w];
        }
        __syncthreads();
        for (int t = tid; t < PER_W; t += 512) {
            float g = 0.f;
#pragma unroll
            for (int b = 0; b < NSUP; b++) g += cb[b] * E[b * PER_W + t];
            vsl[t] -= LRATE * INVT * sesl[t] * g;
        }
        __syncthreads();
    }

    // final export (all local to this class; kernel boundary orders for #6)
    {
        float m = -3.0e38f;
        for (int t = tid; t < PER_W; t += 512) m = fmaxf(m, vsl[t]);
        for (int o = 16; o; o >>= 1)
            m = fmaxf(m, __shfl_xor_sync(0xffffffffu, m, o));
        if (lane == 0) red[warp] = m;
        __syncthreads();
        if (tid == 0) {
            float mm = red[0];
            for (int u = 1; u < 16; u++) mm = fmaxf(mm, red[u]);
            mxs = mm;
            g_mxc[w] = mm * INVT;
        }
        __syncthreads();
        float mx = mxs;
        for (int t = tid; t < PER_W; t += 512)
            g_e[base + t] = __expf((vsl[t] - mx) * INVT);
    }
}

// --------------------------- launch #6: final LSE --------------------------
__global__ __launch_bounds__(128)
void final_kernel(float* __restrict__ out)
{
    int pair = blockIdx.x;
    int b = pair / NWAY, w = pair % NWAY;
    int base = w * PER_W;
    int tid = threadIdx.x;
    float s = 0.f;
    for (int idx = tid; idx < PER_W; idx += 128)
        s += g_e[base + idx] * g_E2t[b * LS + base + idx];
    __shared__ float sh[4];
    for (int o = 16; o; o >>= 1) s += __shfl_down_sync(0xffffffffu, s, o);
    if ((tid & 31) == 0) sh[tid >> 5] = s;
    __syncthreads();
    if (tid == 0)
        out[pair] = logf(sh[0] + sh[1] + sh[2] + sh[3]) + g_mxc[w];
}

// ---------------------------------------------------------------------------
extern "C" void kernel_launch(void* const* d_in, const int* in_sizes, int n_in,
                              void* d_out, int out_size)
{
    const float* sk  = (const float*)d_in[0];
    const float* sq  = (const float*)d_in[1];
    const float* q   = (const float*)d_in[2];
    const int*   lab = (const int*)  d_in[3];
    float*       out = (float*)d_out;

    __half *A, *B;
    cudaGetSymbolAddress((void**)&A, g_A);
    cudaGetSymbolAddress((void**)&B, g_B);

    cudaFuncSetAttribute(gemm_kernel,
                         cudaFuncAttributeMaxDynamicSharedMemorySize, SM_TOTAL);
    cudaFuncSetAttribute(optimize_kernel,
                         cudaFuncAttributeMaxDynamicSharedMemorySize, OPT_SMEM);

    conv_all_kernel<<<MPAD + NPAD, 128>>>(sk, sq, q);                  // #1
    fill_all_kernel<<<((NSUP + NQRY) * LS + 255) / 256, 256>>>();      // #2
    zero_scratch_kernel<<<1, 256>>>();                                 // #3
    dim3 grid(NPAD / 128, MPAD / 128);
    gemm_kernel<<<grid, 256, SM_TOTAL>>>(A, B);                        // #4
    optimize_kernel<<<NOPT, 512, OPT_SMEM>>>(lab);                     // #5
    final_kernel<<<NQRY * NWAY, 128>>>(out);                           // #6
}